// round 2
// baseline (speedup 1.0000x reference)
#include <cuda_runtime.h>
#include <cuda_bf16.h>
#include <math.h>

// Problem constants
#define BB 4
#define SS 2048
#define DD 1024
#define HH 16
#define HD 64
#define ROWS (BB * SS)        // 8192
#define QKV_N (3 * DD)        // 3072

// Scratch buffers (allocation-free rule: __device__ globals)
__device__ float g_qkv[ROWS * QKV_N];      // [8192, 3072]
__device__ float g_attn_out[ROWS * DD];    // [8192, 1024]

// ---------------------------------------------------------------------------
// SGEMM with fused bias: C[M,N] = A[M,K] @ B[K,N] + bias[N]
// 128x128 block, BK=8, 256 threads, 8x8 per-thread register tile.
// ---------------------------------------------------------------------------
#define GBM 128
#define GBN 128
#define GBK 8
#define GTM 8
#define GTN 8

__global__ __launch_bounds__(256, 2)
void gemm_bias_kernel(const float* __restrict__ A, const float* __restrict__ B,
                      const float* __restrict__ bias, float* __restrict__ C,
                      int M, int N, int K) {
    __shared__ float As[GBK][GBM];
    __shared__ float Bs[GBK][GBN];

    const int block_row = blockIdx.y;
    const int block_col = blockIdx.x;
    const int tid = threadIdx.x;

    const int threadCol = tid % (GBN / GTN);   // 0..15
    const int threadRow = tid / (GBN / GTN);   // 0..15

    const int innerRowA = tid / (GBK / 4);     // 0..127
    const int innerColA = tid % (GBK / 4);     // 0..1
    const int innerRowB = tid / (GBN / 4);     // 0..7
    const int innerColB = tid % (GBN / 4);     // 0..31

    const float* Ablk = A + (size_t)block_row * GBM * K;
    const float* Bblk = B + (size_t)block_col * GBN;

    float acc[GTM][GTN];
#pragma unroll
    for (int i = 0; i < GTM; i++)
#pragma unroll
        for (int j = 0; j < GTN; j++) acc[i][j] = 0.0f;

    float regM[GTM], regN[GTN];

    for (int k0 = 0; k0 < K; k0 += GBK) {
        // Load A tile (128x8), store transposed As[k][m]
        float4 a = *(const float4*)(Ablk + (size_t)innerRowA * K + k0 + innerColA * 4);
        As[innerColA * 4 + 0][innerRowA] = a.x;
        As[innerColA * 4 + 1][innerRowA] = a.y;
        As[innerColA * 4 + 2][innerRowA] = a.z;
        As[innerColA * 4 + 3][innerRowA] = a.w;
        // Load B tile (8x128) straight
        float4 b = *(const float4*)(Bblk + (size_t)(k0 + innerRowB) * N + innerColB * 4);
        *(float4*)(&Bs[innerRowB][innerColB * 4]) = b;
        __syncthreads();

#pragma unroll
        for (int d = 0; d < GBK; d++) {
#pragma unroll
            for (int i = 0; i < GTM; i++) regM[i] = As[d][threadRow * GTM + i];
#pragma unroll
            for (int j = 0; j < GTN; j++) regN[j] = Bs[d][threadCol * GTN + j];
#pragma unroll
            for (int i = 0; i < GTM; i++)
#pragma unroll
                for (int j = 0; j < GTN; j++)
                    acc[i][j] = fmaf(regM[i], regN[j], acc[i][j]);
        }
        __syncthreads();
    }

    // Epilogue: bias + vectorized store
#pragma unroll
    for (int i = 0; i < GTM; i++) {
        int row = block_row * GBM + threadRow * GTM + i;
#pragma unroll
        for (int j = 0; j < GTN; j += 4) {
            int col = block_col * GBN + threadCol * GTN + j;
            float4 bv = *(const float4*)(bias + col);
            float4 cv;
            cv.x = acc[i][j + 0] + bv.x;
            cv.y = acc[i][j + 1] + bv.y;
            cv.z = acc[i][j + 2] + bv.z;
            cv.w = acc[i][j + 3] + bv.w;
            *(float4*)(C + (size_t)row * N + col) = cv;
        }
    }
}

// ---------------------------------------------------------------------------
// Flash attention (fp32, causal). One block = (batch b, head h, 64-query tile).
// 256 threads as 16x16 grid, each thread owns a 4(q) x 4(k) score microtile
// and a 4(q) x 4(hd) output microtile.
// Smem: Qs[d][q], Ks[d][k], Vs[k][hd], Ps[k][q], each 64x68 floats (pad 4).
// ---------------------------------------------------------------------------
#define ABM 64
#define ABN 64
#define APAD 68
#define ASM_FLOATS (4 * 64 * APAD)

__global__ __launch_bounds__(256, 2)
void flash_attn_kernel(const float* __restrict__ qkv, float* __restrict__ out) {
    extern __shared__ float sm[];
    float* Qs = sm;                  // [d][q]  64 x 68
    float* Ks = sm + 64 * APAD;      // [d][k]
    float* Vs = sm + 2 * 64 * APAD;  // [k][hd]
    float* Ps = sm + 3 * 64 * APAD;  // [k][q]

    const int qt = blockIdx.x;   // query tile 0..31
    const int h  = blockIdx.y;   // head
    const int b  = blockIdx.z;   // batch

    const int tid = threadIdx.x;
    const int tr = tid / 16;     // q group 0..15
    const int tc = tid % 16;     // k / hd group 0..15

    const int q0 = qt * ABM;
    const size_t row_base = (size_t)b * SS;

    const float scale = 0.125f;  // 1/sqrt(64)

    // Load Q tile (scaled). Each thread: 4 float4 loads.
    {
        const int tok = tid / 16;        // 0..15
        const int d4  = tid % 16;        // 0..15 -> d = d4*4
#pragma unroll
        for (int r = 0; r < 4; r++) {
            int t = r * 16 + tok;        // 0..63
            const float* src = qkv + (row_base + q0 + t) * QKV_N + h * HD + d4 * 4;
            float4 v = *(const float4*)src;
            Qs[(d4 * 4 + 0) * APAD + t] = v.x * scale;
            Qs[(d4 * 4 + 1) * APAD + t] = v.y * scale;
            Qs[(d4 * 4 + 2) * APAD + t] = v.z * scale;
            Qs[(d4 * 4 + 3) * APAD + t] = v.w * scale;
        }
    }

    float o[4][4];
#pragma unroll
    for (int i = 0; i < 4; i++)
#pragma unroll
        for (int j = 0; j < 4; j++) o[i][j] = 0.0f;
    float m_run[4], l_run[4];
#pragma unroll
    for (int i = 0; i < 4; i++) { m_run[i] = -INFINITY; l_run[i] = 0.0f; }

    for (int kt = 0; kt <= qt; kt++) {
        const int k0 = kt * ABN;
        // Load K (transposed to [d][k]) and V (natural [k][hd])
        {
            const int tok = tid / 16;
            const int d4  = tid % 16;
#pragma unroll
            for (int r = 0; r < 4; r++) {
                int t = r * 16 + tok;
                const float* ksrc = qkv + (row_base + k0 + t) * QKV_N + DD + h * HD + d4 * 4;
                float4 kv = *(const float4*)ksrc;
                Ks[(d4 * 4 + 0) * APAD + t] = kv.x;
                Ks[(d4 * 4 + 1) * APAD + t] = kv.y;
                Ks[(d4 * 4 + 2) * APAD + t] = kv.z;
                Ks[(d4 * 4 + 3) * APAD + t] = kv.w;
                const float* vsrc = qkv + (row_base + k0 + t) * QKV_N + 2 * DD + h * HD + d4 * 4;
                float4 vv = *(const float4*)vsrc;
                *(float4*)(&Vs[t * APAD + d4 * 4]) = vv;
            }
        }
        __syncthreads();

        // S = Q^T K (per-thread 4x4)
        float s[4][4];
#pragma unroll
        for (int i = 0; i < 4; i++)
#pragma unroll
            for (int j = 0; j < 4; j++) s[i][j] = 0.0f;

#pragma unroll 8
        for (int d = 0; d < 64; d++) {
            float4 qv = *(const float4*)(&Qs[d * APAD + tr * 4]);
            float4 kv = *(const float4*)(&Ks[d * APAD + tc * 4]);
            float qa[4] = {qv.x, qv.y, qv.z, qv.w};
            float ka[4] = {kv.x, kv.y, kv.z, kv.w};
#pragma unroll
            for (int i = 0; i < 4; i++)
#pragma unroll
                for (int j = 0; j < 4; j++)
                    s[i][j] = fmaf(qa[i], ka[j], s[i][j]);
        }

        // Causal mask (only diagonal tile needs it)
        if (kt == qt) {
#pragma unroll
            for (int i = 0; i < 4; i++) {
                int qg = q0 + tr * 4 + i;
#pragma unroll
                for (int j = 0; j < 4; j++) {
                    int kg = k0 + tc * 4 + j;
                    if (kg > qg) s[i][j] = -INFINITY;
                }
            }
        }

        // Online softmax: row stats across the 16 threads sharing a q row
        float m_new[4], alpha[4];
#pragma unroll
        for (int i = 0; i < 4; i++) {
            float mx = s[i][0];
            mx = fmaxf(mx, s[i][1]); mx = fmaxf(mx, s[i][2]); mx = fmaxf(mx, s[i][3]);
#pragma unroll
            for (int w = 1; w < 16; w <<= 1)
                mx = fmaxf(mx, __shfl_xor_sync(0xffffffffu, mx, w));
            m_new[i] = fmaxf(m_run[i], mx);
        }
#pragma unroll
        for (int i = 0; i < 4; i++) {
            float rs = 0.0f;
#pragma unroll
            for (int j = 0; j < 4; j++) {
                float p = __expf(s[i][j] - m_new[i]);
                s[i][j] = p;
                rs += p;
            }
#pragma unroll
            for (int w = 1; w < 16; w <<= 1)
                rs += __shfl_xor_sync(0xffffffffu, rs, w);
            alpha[i] = __expf(m_run[i] - m_new[i]);
            l_run[i] = l_run[i] * alpha[i] + rs;
            m_run[i] = m_new[i];
#pragma unroll
            for (int j = 0; j < 4; j++) o[i][j] *= alpha[i];
        }

        // Write P transposed: Ps[k][q]
#pragma unroll
        for (int i = 0; i < 4; i++)
#pragma unroll
            for (int j = 0; j < 4; j++)
                Ps[(tc * 4 + j) * APAD + (tr * 4 + i)] = s[i][j];
        __syncthreads();

        // O += P @ V  (loop over 64 keys)
#pragma unroll 8
        for (int kk = 0; kk < 64; kk++) {
            float4 pv = *(const float4*)(&Ps[kk * APAD + tr * 4]);
            float4 vv = *(const float4*)(&Vs[kk * APAD + tc * 4]);
            float pa[4] = {pv.x, pv.y, pv.z, pv.w};
            float va[4] = {vv.x, vv.y, vv.z, vv.w};
#pragma unroll
            for (int i = 0; i < 4; i++)
#pragma unroll
                for (int j = 0; j < 4; j++)
                    o[i][j] = fmaf(pa[i], va[j], o[i][j]);
        }
        __syncthreads();
    }

    // Epilogue: normalize and store to attn_out [row, h*64 + hd]
#pragma unroll
    for (int i = 0; i < 4; i++) {
        float inv_l = 1.0f / l_run[i];
        size_t row = row_base + q0 + tr * 4 + i;
        float4 ov;
        ov.x = o[i][0] * inv_l;
        ov.y = o[i][1] * inv_l;
        ov.z = o[i][2] * inv_l;
        ov.w = o[i][3] * inv_l;
        *(float4*)(out + row * DD + h * HD + tc * 4) = ov;
    }
}

// ---------------------------------------------------------------------------
// Launch
// ---------------------------------------------------------------------------
extern "C" void kernel_launch(void* const* d_in, const int* in_sizes, int n_in,
                              void* d_out, int out_size) {
    const float* x      = (const float*)d_in[0];
    const float* W_attn = (const float*)d_in[1];
    const float* b_attn = (const float*)d_in[2];
    const float* W_proj = (const float*)d_in[3];
    const float* b_proj = (const float*)d_in[4];
    float* out = (float*)d_out;

    float* qkv = nullptr;
    float* attn_out = nullptr;
    cudaGetSymbolAddress((void**)&qkv, g_qkv);
    cudaGetSymbolAddress((void**)&attn_out, g_attn_out);

    // Flash kernel needs 68KB dynamic smem
    static const size_t flash_smem = ASM_FLOATS * sizeof(float);
    cudaFuncSetAttribute(flash_attn_kernel,
                         cudaFuncAttributeMaxDynamicSharedMemorySize,
                         (int)flash_smem);

    // 1) QKV projection: [8192,3072] = x[8192,1024] @ W_attn + b_attn
    {
        dim3 grid(QKV_N / GBN, ROWS / GBM);
        gemm_bias_kernel<<<grid, 256>>>(x, W_attn, b_attn, qkv, ROWS, QKV_N, DD);
    }

    // 2) Flash attention
    {
        dim3 grid(SS / ABM, HH, BB);
        flash_attn_kernel<<<grid, 256, flash_smem>>>(qkv, attn_out);
    }

    // 3) Output projection: out = attn_out @ W_proj + b_proj
    {
        dim3 grid(DD / GBN, ROWS / GBM);
        gemm_bias_kernel<<<grid, 256>>>(attn_out, W_proj, b_proj, out, ROWS, DD, DD);
    }
}

// round 4
// speedup vs baseline: 1.2697x; 1.2697x over previous
#include <cuda_runtime.h>
#include <cuda_bf16.h>
#include <math.h>
#include <stdint.h>

// Problem constants
#define BB 4
#define SS 2048
#define DD 1024
#define HH 16
#define HD 64
#define ROWS (BB * SS)        // 8192
#define QKV_N (3 * DD)        // 3072

// Scratch buffers (allocation-free rule: __device__ globals)
__device__ float g_qkv[ROWS * QKV_N];      // [8192, 3072]
__device__ float g_attn_out[ROWS * DD];    // [8192, 1024]

__device__ __forceinline__ uint32_t smem_u32(const void* p) {
    uint32_t a;
    asm("{ .reg .u64 t; cvta.to.shared.u64 t, %1; cvt.u32.u64 %0, t; }" : "=r"(a) : "l"(p));
    return a;
}

// Split one float into bf16 hi + bf16 lo (x ~= hi + lo), packed pairwise.
__device__ __forceinline__ void split_pack(float x, float y, uint32_t& h, uint32_t& l) {
    __nv_bfloat16 hx = __float2bfloat16(x), hy = __float2bfloat16(y);
    float rx = x - __bfloat162float(hx);
    float ry = y - __bfloat162float(hy);
    __nv_bfloat16 lx = __float2bfloat16(rx), ly = __float2bfloat16(ry);
    h = ((uint32_t)__bfloat16_as_ushort(hy) << 16) | (uint32_t)__bfloat16_as_ushort(hx);
    l = ((uint32_t)__bfloat16_as_ushort(ly) << 16) | (uint32_t)__bfloat16_as_ushort(lx);
}

#define LDMATRIX_X4(r0, r1, r2, r3, addr) \
    asm volatile("ldmatrix.sync.aligned.m8n8.x4.shared.b16 {%0,%1,%2,%3}, [%4];" \
        : "=r"(r0), "=r"(r1), "=r"(r2), "=r"(r3) : "r"(addr))

#define MMA_BF16(d, a, b) \
    asm volatile("mma.sync.aligned.m16n8k16.row.col.f32.bf16.bf16.f32 " \
        "{%0,%1,%2,%3}, {%4,%5,%6,%7}, {%8,%9}, {%0,%1,%2,%3};" \
        : "+f"((d)[0]), "+f"((d)[1]), "+f"((d)[2]), "+f"((d)[3]) \
        : "r"((a)[0]), "r"((a)[1]), "r"((a)[2]), "r"((a)[3]), \
          "r"((b)[0]), "r"((b)[1]))

// ---------------------------------------------------------------------------
// bf16-split tensor-core GEMM: C[M,N] = A[M,K] @ B[K,N] + bias[N]
// CTA tile 128x128, BK=32, 256 threads (8 warps as 4(M) x 2(N)).
// Smem: Ah/Al [128][32] bf16 and Bh/Bl [n=128][k=32] bf16, row stride 80B
// (64B data + 16B pad -> conflict-free ldmatrix).
// ---------------------------------------------------------------------------
#define GSTRIDE 80
#define GSM_A_HI 0
#define GSM_A_LO 10240
#define GSM_B_HI 20480
#define GSM_B_LO 30720

__global__ void __launch_bounds__(256)
gemm_tc_kernel(const float* __restrict__ A, const float* __restrict__ B,
               const float* __restrict__ bias, float* __restrict__ C,
               int N, int K) {
    __shared__ __align__(16) unsigned char sm_raw[40960];
    const uint32_t sb = smem_u32(sm_raw);

    const int tid = threadIdx.x;
    const int wid = tid >> 5;
    const int lid = tid & 31;
    const int warp_m = wid & 3;   // 0..3 -> 32 rows each
    const int warp_n = wid >> 2;  // 0..1 -> 64 cols each

    const int m0 = blockIdx.y * 128;
    const int n0 = blockIdx.x * 128;

    // A fill indexing: row r=tid/2, 16-col segment seg=tid%2
    const int fa_r = tid >> 1;
    const int fa_seg = tid & 1;
    const float* fa_src = A + (size_t)(m0 + fa_r) * K + fa_seg * 16;
    // B fill indexing: 4x4 block: k0=4*(tid/32), n0b=4*(tid%32)
    const int fb_k = (tid >> 5) * 4;
    const int fb_n = (tid & 31) * 4;
    const float* fb_src = B + (size_t)fb_k * N + n0 + fb_n;

    float acc[2][8][4];
#pragma unroll
    for (int i = 0; i < 2; i++)
#pragma unroll
        for (int j = 0; j < 8; j++)
#pragma unroll
            for (int v = 0; v < 4; v++) acc[i][j][v] = 0.0f;

    float a_pf[16];
    float b_pf[16];

    // ldmatrix lane addresses (constant across chunks)
    // A frag (m16k16 at mt, ks): m = warp_m*32 + mt*16 + lid%16 ; kbyte = ks*32 + (lid/16)*16
    const uint32_t a_lane_row = (uint32_t)(warp_m * 32 + (lid & 15));
    const uint32_t a_lane_kb = (uint32_t)((lid >> 4) * 16);
    // B frag (n16k16 pair at pb, ks): n = warp_n*64 + pb*16 + (lid%8) + ((lid>>4)&1)*8
    //                                 kbyte = ks*32 + ((lid>>3)&1)*16
    const uint32_t b_lane_row = (uint32_t)(warp_n * 64 + (lid & 7) + ((lid >> 4) & 1) * 8);
    const uint32_t b_lane_kb = (uint32_t)(((lid >> 3) & 1) * 16);

    const int nchunks = K >> 5;

    // Prefetch chunk 0
#pragma unroll
    for (int j = 0; j < 4; j++)
        *(float4*)(a_pf + j * 4) = *(const float4*)(fa_src + j * 4);
#pragma unroll
    for (int j = 0; j < 4; j++)
        *(float4*)(b_pf + j * 4) = *(const float4*)(fb_src + (size_t)j * N);

    for (int kc = 0; kc < nchunks; kc++) {
        // ---- Convert + store prefetched regs to smem ----
        {
            uint32_t hu[8], lu[8];
#pragma unroll
            for (int j = 0; j < 8; j++)
                split_pack(a_pf[2 * j], a_pf[2 * j + 1], hu[j], lu[j]);
            unsigned char* dst_h = sm_raw + GSM_A_HI + fa_r * GSTRIDE + fa_seg * 32;
            unsigned char* dst_l = sm_raw + GSM_A_LO + fa_r * GSTRIDE + fa_seg * 32;
            *(uint4*)dst_h = make_uint4(hu[0], hu[1], hu[2], hu[3]);
            *(uint4*)(dst_h + 16) = make_uint4(hu[4], hu[5], hu[6], hu[7]);
            *(uint4*)dst_l = make_uint4(lu[0], lu[1], lu[2], lu[3]);
            *(uint4*)(dst_l + 16) = make_uint4(lu[4], lu[5], lu[6], lu[7]);
        }
        {
            // b_pf[j*4+i] = B[k0+j][n0b+i]; transpose to per-n k-runs
#pragma unroll
            for (int i = 0; i < 4; i++) {
                uint32_t h0, l0, h1, l1;
                split_pack(b_pf[0 * 4 + i], b_pf[1 * 4 + i], h0, l0);
                split_pack(b_pf[2 * 4 + i], b_pf[3 * 4 + i], h1, l1);
                unsigned char* dh = sm_raw + GSM_B_HI + (fb_n + i) * GSTRIDE + fb_k * 2;
                unsigned char* dl = sm_raw + GSM_B_LO + (fb_n + i) * GSTRIDE + fb_k * 2;
                *(uint2*)dh = make_uint2(h0, h1);
                *(uint2*)dl = make_uint2(l0, l1);
            }
        }
        __syncthreads();

        // ---- Prefetch next chunk (overlaps with MMA below) ----
        if (kc + 1 < nchunks) {
            const float* an = fa_src + (kc + 1) * 32;
            const float* bn = fb_src + (size_t)(kc + 1) * 32 * N;
#pragma unroll
            for (int j = 0; j < 4; j++)
                *(float4*)(a_pf + j * 4) = *(const float4*)(an + j * 4);
#pragma unroll
            for (int j = 0; j < 4; j++)
                *(float4*)(b_pf + j * 4) = *(const float4*)(bn + (size_t)j * N);
        }

        // ---- MMA over this chunk: 2 k-steps of 16 ----
#pragma unroll
        for (int ks = 0; ks < 2; ks++) {
            uint32_t ah[2][4], al[2][4], bh[8][2], bl[8][2];
#pragma unroll
            for (int mt = 0; mt < 2; mt++) {
                uint32_t addr = sb + GSM_A_HI +
                    (a_lane_row + mt * 16) * GSTRIDE + ks * 32 + a_lane_kb;
                LDMATRIX_X4(ah[mt][0], ah[mt][1], ah[mt][2], ah[mt][3], addr);
                LDMATRIX_X4(al[mt][0], al[mt][1], al[mt][2], al[mt][3],
                            addr + (GSM_A_LO - GSM_A_HI));
            }
#pragma unroll
            for (int pb = 0; pb < 4; pb++) {
                uint32_t r0, r1, r2, r3;
                uint32_t addr = sb + GSM_B_HI +
                    (b_lane_row + pb * 16) * GSTRIDE + ks * 32 + b_lane_kb;
                LDMATRIX_X4(r0, r1, r2, r3, addr);
                bh[2 * pb][0] = r0; bh[2 * pb][1] = r1;
                bh[2 * pb + 1][0] = r2; bh[2 * pb + 1][1] = r3;
                LDMATRIX_X4(r0, r1, r2, r3, addr + (GSM_B_LO - GSM_B_HI));
                bl[2 * pb][0] = r0; bl[2 * pb][1] = r1;
                bl[2 * pb + 1][0] = r2; bl[2 * pb + 1][1] = r3;
            }
#pragma unroll
            for (int mt = 0; mt < 2; mt++)
#pragma unroll
                for (int nt = 0; nt < 8; nt++) {
                    MMA_BF16(acc[mt][nt], ah[mt], bh[nt]);
                    MMA_BF16(acc[mt][nt], ah[mt], bl[nt]);
                    MMA_BF16(acc[mt][nt], al[mt], bh[nt]);
                }
        }
        __syncthreads();
    }

    // ---- Epilogue: bias + store ----
#pragma unroll
    for (int mt = 0; mt < 2; mt++) {
        int r0 = m0 + warp_m * 32 + mt * 16 + (lid >> 2);
#pragma unroll
        for (int nt = 0; nt < 8; nt++) {
            int col = n0 + warp_n * 64 + nt * 8 + (lid & 3) * 2;
            float2 bv = *(const float2*)(bias + col);
            float2 c0, c1;
            c0.x = acc[mt][nt][0] + bv.x;
            c0.y = acc[mt][nt][1] + bv.y;
            c1.x = acc[mt][nt][2] + bv.x;
            c1.y = acc[mt][nt][3] + bv.y;
            *(float2*)(C + (size_t)r0 * N + col) = c0;
            *(float2*)(C + (size_t)(r0 + 8) * N + col) = c1;
        }
    }
}

// ---------------------------------------------------------------------------
// Flash attention (fp32, causal) — unchanged from the passing round-1 kernel.
// ---------------------------------------------------------------------------
#define ABM 64
#define ABN 64
#define APAD 68
#define ASM_FLOATS (4 * 64 * APAD)

__global__ __launch_bounds__(256, 2)
void flash_attn_kernel(const float* __restrict__ qkv, float* __restrict__ out) {
    extern __shared__ float sm[];
    float* Qs = sm;
    float* Ks = sm + 64 * APAD;
    float* Vs = sm + 2 * 64 * APAD;
    float* Ps = sm + 3 * 64 * APAD;

    const int qt = blockIdx.x;
    const int h  = blockIdx.y;
    const int b  = blockIdx.z;

    const int tid = threadIdx.x;
    const int tr = tid / 16;
    const int tc = tid % 16;

    const int q0 = qt * ABM;
    const size_t row_base = (size_t)b * SS;
    const float scale = 0.125f;

    {
        const int tok = tid / 16;
        const int d4  = tid % 16;
#pragma unroll
        for (int r = 0; r < 4; r++) {
            int t = r * 16 + tok;
            const float* src = qkv + (row_base + q0 + t) * QKV_N + h * HD + d4 * 4;
            float4 v = *(const float4*)src;
            Qs[(d4 * 4 + 0) * APAD + t] = v.x * scale;
            Qs[(d4 * 4 + 1) * APAD + t] = v.y * scale;
            Qs[(d4 * 4 + 2) * APAD + t] = v.z * scale;
            Qs[(d4 * 4 + 3) * APAD + t] = v.w * scale;
        }
    }

    float o[4][4];
#pragma unroll
    for (int i = 0; i < 4; i++)
#pragma unroll
        for (int j = 0; j < 4; j++) o[i][j] = 0.0f;
    float m_run[4], l_run[4];
#pragma unroll
    for (int i = 0; i < 4; i++) { m_run[i] = -INFINITY; l_run[i] = 0.0f; }

    for (int kt = 0; kt <= qt; kt++) {
        const int k0 = kt * ABN;
        {
            const int tok = tid / 16;
            const int d4  = tid % 16;
#pragma unroll
            for (int r = 0; r < 4; r++) {
                int t = r * 16 + tok;
                const float* ksrc = qkv + (row_base + k0 + t) * QKV_N + DD + h * HD + d4 * 4;
                float4 kv = *(const float4*)ksrc;
                Ks[(d4 * 4 + 0) * APAD + t] = kv.x;
                Ks[(d4 * 4 + 1) * APAD + t] = kv.y;
                Ks[(d4 * 4 + 2) * APAD + t] = kv.z;
                Ks[(d4 * 4 + 3) * APAD + t] = kv.w;
                const float* vsrc = qkv + (row_base + k0 + t) * QKV_N + 2 * DD + h * HD + d4 * 4;
                float4 vv = *(const float4*)vsrc;
                *(float4*)(&Vs[t * APAD + d4 * 4]) = vv;
            }
        }
        __syncthreads();

        float s[4][4];
#pragma unroll
        for (int i = 0; i < 4; i++)
#pragma unroll
            for (int j = 0; j < 4; j++) s[i][j] = 0.0f;

#pragma unroll 8
        for (int d = 0; d < 64; d++) {
            float4 qv = *(const float4*)(&Qs[d * APAD + tr * 4]);
            float4 kv = *(const float4*)(&Ks[d * APAD + tc * 4]);
            float qa[4] = {qv.x, qv.y, qv.z, qv.w};
            float ka[4] = {kv.x, kv.y, kv.z, kv.w};
#pragma unroll
            for (int i = 0; i < 4; i++)
#pragma unroll
                for (int j = 0; j < 4; j++)
                    s[i][j] = fmaf(qa[i], ka[j], s[i][j]);
        }

        if (kt == qt) {
#pragma unroll
            for (int i = 0; i < 4; i++) {
                int qg = q0 + tr * 4 + i;
#pragma unroll
                for (int j = 0; j < 4; j++) {
                    int kg = k0 + tc * 4 + j;
                    if (kg > qg) s[i][j] = -INFINITY;
                }
            }
        }

        float m_new[4], alpha[4];
#pragma unroll
        for (int i = 0; i < 4; i++) {
            float mx = s[i][0];
            mx = fmaxf(mx, s[i][1]); mx = fmaxf(mx, s[i][2]); mx = fmaxf(mx, s[i][3]);
#pragma unroll
            for (int w = 1; w < 16; w <<= 1)
                mx = fmaxf(mx, __shfl_xor_sync(0xffffffffu, mx, w));
            m_new[i] = fmaxf(m_run[i], mx);
        }
#pragma unroll
        for (int i = 0; i < 4; i++) {
            float rs = 0.0f;
#pragma unroll
            for (int j = 0; j < 4; j++) {
                float p = __expf(s[i][j] - m_new[i]);
                s[i][j] = p;
                rs += p;
            }
#pragma unroll
            for (int w = 1; w < 16; w <<= 1)
                rs += __shfl_xor_sync(0xffffffffu, rs, w);
            alpha[i] = __expf(m_run[i] - m_new[i]);
            l_run[i] = l_run[i] * alpha[i] + rs;
            m_run[i] = m_new[i];
#pragma unroll
            for (int j = 0; j < 4; j++) o[i][j] *= alpha[i];
        }

#pragma unroll
        for (int i = 0; i < 4; i++)
#pragma unroll
            for (int j = 0; j < 4; j++)
                Ps[(tc * 4 + j) * APAD + (tr * 4 + i)] = s[i][j];
        __syncthreads();

#pragma unroll 8
        for (int kk = 0; kk < 64; kk++) {
            float4 pv = *(const float4*)(&Ps[kk * APAD + tr * 4]);
            float4 vv = *(const float4*)(&Vs[kk * APAD + tc * 4]);
            float pa[4] = {pv.x, pv.y, pv.z, pv.w};
            float va[4] = {vv.x, vv.y, vv.z, vv.w};
#pragma unroll
            for (int i = 0; i < 4; i++)
#pragma unroll
                for (int j = 0; j < 4; j++)
                    o[i][j] = fmaf(pa[i], va[j], o[i][j]);
        }
        __syncthreads();
    }

#pragma unroll
    for (int i = 0; i < 4; i++) {
        float inv_l = 1.0f / l_run[i];
        size_t row = row_base + q0 + tr * 4 + i;
        float4 ov;
        ov.x = o[i][0] * inv_l;
        ov.y = o[i][1] * inv_l;
        ov.z = o[i][2] * inv_l;
        ov.w = o[i][3] * inv_l;
        *(float4*)(out + row * DD + h * HD + tc * 4) = ov;
    }
}

// ---------------------------------------------------------------------------
// Launch
// ---------------------------------------------------------------------------
extern "C" void kernel_launch(void* const* d_in, const int* in_sizes, int n_in,
                              void* d_out, int out_size) {
    const float* x      = (const float*)d_in[0];
    const float* W_attn = (const float*)d_in[1];
    const float* b_attn = (const float*)d_in[2];
    const float* W_proj = (const float*)d_in[3];
    const float* b_proj = (const float*)d_in[4];
    float* out = (float*)d_out;

    float* qkv = nullptr;
    float* attn_out = nullptr;
    cudaGetSymbolAddress((void**)&qkv, g_qkv);
    cudaGetSymbolAddress((void**)&attn_out, g_attn_out);

    static const size_t flash_smem = ASM_FLOATS * sizeof(float);
    cudaFuncSetAttribute(flash_attn_kernel,
                         cudaFuncAttributeMaxDynamicSharedMemorySize,
                         (int)flash_smem);

    // 1) QKV projection: [8192,3072] = x @ W_attn + b_attn
    {
        dim3 grid(QKV_N / 128, ROWS / 128);
        gemm_tc_kernel<<<grid, 256>>>(x, W_attn, b_attn, qkv, QKV_N, DD);
    }
    // 2) Flash attention
    {
        dim3 grid(SS / ABM, HH, BB);
        flash_attn_kernel<<<grid, 256, flash_smem>>>(qkv, attn_out);
    }
    // 3) Output projection: out = attn_out @ W_proj + b_proj
    {
        dim3 grid(DD / 128, ROWS / 128);
        gemm_tc_kernel<<<grid, 256>>>(attn_out, W_proj, b_proj, out, DD, DD);
    }
}

// round 5
// speedup vs baseline: 1.5833x; 1.2470x over previous
#include <cuda_runtime.h>
#include <cuda_bf16.h>
#include <math.h>
#include <stdint.h>

// Problem constants
#define BB 4
#define SS 2048
#define DD 1024
#define HH 16
#define HD 64
#define ROWS (BB * SS)        // 8192
#define QKV_N (3 * DD)        // 3072

// Scratch buffers (allocation-free rule: __device__ globals)
__device__ float g_qkv[ROWS * QKV_N];                       // fp32 qkv for flash
__device__ __align__(16) __nv_bfloat16 g_xh[ROWS * DD];     // x split hi
__device__ __align__(16) __nv_bfloat16 g_xl[ROWS * DD];     // x split lo
__device__ __align__(16) __nv_bfloat16 g_aoh[ROWS * DD];    // attn out split hi
__device__ __align__(16) __nv_bfloat16 g_aol[ROWS * DD];    // attn out split lo
__device__ __align__(16) __nv_bfloat16 g_wah[QKV_N * DD];   // W_attn^T hi [3072][1024]
__device__ __align__(16) __nv_bfloat16 g_wal[QKV_N * DD];   // W_attn^T lo
__device__ __align__(16) __nv_bfloat16 g_wph[DD * DD];      // W_proj^T hi [1024][1024]
__device__ __align__(16) __nv_bfloat16 g_wpl[DD * DD];      // W_proj^T lo

__device__ __forceinline__ uint32_t smem_u32(const void* p) {
    uint32_t a;
    asm("{ .reg .u64 t; cvta.to.shared.u64 t, %1; cvt.u32.u64 %0, t; }" : "=r"(a) : "l"(p));
    return a;
}

__device__ __forceinline__ void split_pack(float x, float y, uint32_t& h, uint32_t& l) {
    __nv_bfloat16 hx = __float2bfloat16(x), hy = __float2bfloat16(y);
    float rx = x - __bfloat162float(hx);
    float ry = y - __bfloat162float(hy);
    __nv_bfloat16 lx = __float2bfloat16(rx), ly = __float2bfloat16(ry);
    h = ((uint32_t)__bfloat16_as_ushort(hy) << 16) | (uint32_t)__bfloat16_as_ushort(hx);
    l = ((uint32_t)__bfloat16_as_ushort(ly) << 16) | (uint32_t)__bfloat16_as_ushort(lx);
}

#define LDMATRIX_X4(r0, r1, r2, r3, addr) \
    asm volatile("ldmatrix.sync.aligned.m8n8.x4.shared.b16 {%0,%1,%2,%3}, [%4];" \
        : "=r"(r0), "=r"(r1), "=r"(r2), "=r"(r3) : "r"(addr))

#define MMA_BF16(d, a, b) \
    asm volatile("mma.sync.aligned.m16n8k16.row.col.f32.bf16.bf16.f32 " \
        "{%0,%1,%2,%3}, {%4,%5,%6,%7}, {%8,%9}, {%0,%1,%2,%3};" \
        : "+f"((d)[0]), "+f"((d)[1]), "+f"((d)[2]), "+f"((d)[3]) \
        : "r"((a)[0]), "r"((a)[1]), "r"((a)[2]), "r"((a)[3]), \
          "r"((b)[0]), "r"((b)[1]))

#define CP16(dst, src) \
    asm volatile("cp.async.cg.shared.global [%0], [%1], 16;" :: "r"(dst), "l"(src))
#define CP_COMMIT() asm volatile("cp.async.commit_group;")
#define CP_WAIT0()  asm volatile("cp.async.wait_group 0;" ::: "memory")

// ---------------------------------------------------------------------------
// Pre-split kernels
// ---------------------------------------------------------------------------
__global__ void split_kernel(const float4* __restrict__ src,
                             uint2* __restrict__ hi, uint2* __restrict__ lo, int n4) {
    int i = blockIdx.x * 256 + threadIdx.x;
    if (i >= n4) return;
    float4 v = src[i];
    uint32_t h0, l0, h1, l1;
    split_pack(v.x, v.y, h0, l0);
    split_pack(v.z, v.w, h1, l1);
    hi[i] = make_uint2(h0, h1);
    lo[i] = make_uint2(l0, l1);
}

// W[K][N] fp32 -> Wh/Wl[N][K] bf16 (transpose + split)
__global__ void split_wT_kernel(const float* __restrict__ W,
                                __nv_bfloat16* __restrict__ Wh,
                                __nv_bfloat16* __restrict__ Wl, int K, int N) {
    __shared__ float t[32][33];
    const int n0 = blockIdx.x * 32, k0 = blockIdx.y * 32;
    const int tx = threadIdx.x, ty = threadIdx.y;
#pragma unroll
    for (int j = 0; j < 32; j += 8)
        t[ty + j][tx] = W[(size_t)(k0 + ty + j) * N + n0 + tx];
    __syncthreads();
#pragma unroll
    for (int j = 0; j < 32; j += 8) {
        float v = t[tx][ty + j];
        __nv_bfloat16 h = __float2bfloat16(v);
        __nv_bfloat16 l = __float2bfloat16(v - __bfloat162float(h));
        size_t o = (size_t)(n0 + ty + j) * K + k0 + tx;
        Wh[o] = h;
        Wl[o] = l;
    }
}

// ---------------------------------------------------------------------------
// bf16-split tensor-core GEMM (pre-split operands, cp.async double buffer).
// C[M,N] = (Ah+Al)[M,K] @ (Bh+Bl)^T[N,K] + bias, dropping Al*Bl.
// CTA 128x128, BK=32, 256 threads (8 warps 4Mx2N), 2-stage pipeline.
// Smem per stage: Ah/Al [128 rows][32 bf16] + Bh/Bl [128 n][32 bf16], stride 80B.
// ---------------------------------------------------------------------------
#define GSTRIDE 80
#define STG_A_HI 0
#define STG_A_LO 10240
#define STG_B_HI 20480
#define STG_B_LO 30720
#define STAGE_BYTES 40960
#define GEMM_SMEM (2 * STAGE_BYTES)

__global__ void __launch_bounds__(256, 2)
gemm_bf16_kernel(const __nv_bfloat16* __restrict__ Ah, const __nv_bfloat16* __restrict__ Al,
                 const __nv_bfloat16* __restrict__ Bh, const __nv_bfloat16* __restrict__ Bl,
                 const float* __restrict__ bias, float* __restrict__ C,
                 int N, int K) {
    extern __shared__ __align__(16) unsigned char smem[];
    const uint32_t sb = smem_u32(smem);

    const int tid = threadIdx.x;
    const int wid = tid >> 5;
    const int lid = tid & 31;
    const int warp_m = wid & 3;
    const int warp_n = wid >> 2;

    const int m0 = blockIdx.y * 128;
    const int n0 = blockIdx.x * 128;

    // Fill indexing: each thread copies 2 16B chunks per matrix per stage.
    const int fr = tid >> 2;        // row 0..63 (and +64)
    const int seg = tid & 3;        // 16B segment within 64B row

    const __nv_bfloat16* a_h = Ah + (size_t)(m0 + fr) * K + seg * 8;
    const __nv_bfloat16* a_l = Al + (size_t)(m0 + fr) * K + seg * 8;
    const __nv_bfloat16* b_h = Bh + (size_t)(n0 + fr) * K + seg * 8;
    const __nv_bfloat16* b_l = Bl + (size_t)(n0 + fr) * K + seg * 8;

    float acc[2][8][4];
#pragma unroll
    for (int i = 0; i < 2; i++)
#pragma unroll
        for (int j = 0; j < 8; j++)
#pragma unroll
            for (int v = 0; v < 4; v++) acc[i][j][v] = 0.0f;

    // ldmatrix lane addressing (validated in previous passing round)
    const uint32_t a_lane_row = (uint32_t)(warp_m * 32 + (lid & 15));
    const uint32_t a_lane_kb = (uint32_t)((lid >> 4) * 16);
    const uint32_t b_lane_row = (uint32_t)(warp_n * 64 + (lid & 7) + ((lid >> 4) & 1) * 8);
    const uint32_t b_lane_kb = (uint32_t)(((lid >> 3) & 1) * 16);

    const uint32_t doff = (uint32_t)(fr * GSTRIDE + seg * 16);

    auto fill = [&](int s, int kc) {
        const uint32_t base = sb + s * STAGE_BYTES;
        const size_t ko = (size_t)kc * 32;
        CP16(base + STG_A_HI + doff, a_h + ko);
        CP16(base + STG_A_HI + doff + 64 * GSTRIDE, a_h + ko + (size_t)64 * K);
        CP16(base + STG_A_LO + doff, a_l + ko);
        CP16(base + STG_A_LO + doff + 64 * GSTRIDE, a_l + ko + (size_t)64 * K);
        CP16(base + STG_B_HI + doff, b_h + ko);
        CP16(base + STG_B_HI + doff + 64 * GSTRIDE, b_h + ko + (size_t)64 * K);
        CP16(base + STG_B_LO + doff, b_l + ko);
        CP16(base + STG_B_LO + doff + 64 * GSTRIDE, b_l + ko + (size_t)64 * K);
    };

    auto do_mma = [&](int s) {
        const uint32_t base = sb + s * STAGE_BYTES;
#pragma unroll
        for (int ks = 0; ks < 2; ks++) {
            uint32_t ah[2][4], al[2][4];
#pragma unroll
            for (int mt = 0; mt < 2; mt++) {
                uint32_t addr = base + STG_A_HI +
                    (a_lane_row + mt * 16) * GSTRIDE + ks * 32 + a_lane_kb;
                LDMATRIX_X4(ah[mt][0], ah[mt][1], ah[mt][2], ah[mt][3], addr);
                LDMATRIX_X4(al[mt][0], al[mt][1], al[mt][2], al[mt][3],
                            addr + (STG_A_LO - STG_A_HI));
            }
#pragma unroll
            for (int pb = 0; pb < 4; pb++) {
                uint32_t bh0[2], bh1[2], bl0[2], bl1[2];
                uint32_t addr = base + STG_B_HI +
                    (b_lane_row + pb * 16) * GSTRIDE + ks * 32 + b_lane_kb;
                LDMATRIX_X4(bh0[0], bh0[1], bh1[0], bh1[1], addr);
                LDMATRIX_X4(bl0[0], bl0[1], bl1[0], bl1[1],
                            addr + (STG_B_LO - STG_B_HI));
#pragma unroll
                for (int mt = 0; mt < 2; mt++) {
                    MMA_BF16(acc[mt][2 * pb], ah[mt], bh0);
                    MMA_BF16(acc[mt][2 * pb], ah[mt], bl0);
                    MMA_BF16(acc[mt][2 * pb], al[mt], bh0);
                    MMA_BF16(acc[mt][2 * pb + 1], ah[mt], bh1);
                    MMA_BF16(acc[mt][2 * pb + 1], ah[mt], bl1);
                    MMA_BF16(acc[mt][2 * pb + 1], al[mt], bh1);
                }
            }
        }
    };

    const int nchunks = K >> 5;
    fill(0, 0);
    CP_COMMIT();

    for (int kc = 0; kc < nchunks; kc++) {
        CP_WAIT0();
        __syncthreads();
        if (kc + 1 < nchunks) {
            fill((kc + 1) & 1, kc + 1);
            CP_COMMIT();
        }
        do_mma(kc & 1);
        __syncthreads();
    }

    // Epilogue: bias + store fp32
#pragma unroll
    for (int mt = 0; mt < 2; mt++) {
        int r0 = m0 + warp_m * 32 + mt * 16 + (lid >> 2);
#pragma unroll
        for (int nt = 0; nt < 8; nt++) {
            int col = n0 + warp_n * 64 + nt * 8 + (lid & 3) * 2;
            float2 bv = *(const float2*)(bias + col);
            float2 c0, c1;
            c0.x = acc[mt][nt][0] + bv.x;
            c0.y = acc[mt][nt][1] + bv.y;
            c1.x = acc[mt][nt][2] + bv.x;
            c1.y = acc[mt][nt][3] + bv.y;
            *(float2*)(C + (size_t)r0 * N + col) = c0;
            *(float2*)(C + (size_t)(r0 + 8) * N + col) = c1;
        }
    }
}

// ---------------------------------------------------------------------------
// Flash attention (fp32, causal). Epilogue writes split bf16 hi/lo directly.
// ---------------------------------------------------------------------------
#define ABM 64
#define ABN 64
#define APAD 68
#define ASM_FLOATS (4 * 64 * APAD)

__global__ __launch_bounds__(256, 2)
void flash_attn_kernel(const float* __restrict__ qkv,
                       __nv_bfloat16* __restrict__ aoh,
                       __nv_bfloat16* __restrict__ aol) {
    extern __shared__ float sm[];
    float* Qs = sm;
    float* Ks = sm + 64 * APAD;
    float* Vs = sm + 2 * 64 * APAD;
    float* Ps = sm + 3 * 64 * APAD;

    const int qt = blockIdx.x;
    const int h  = blockIdx.y;
    const int b  = blockIdx.z;

    const int tid = threadIdx.x;
    const int tr = tid / 16;
    const int tc = tid % 16;

    const int q0 = qt * ABM;
    const size_t row_base = (size_t)b * SS;
    const float scale = 0.125f;

    {
        const int tok = tid / 16;
        const int d4  = tid % 16;
#pragma unroll
        for (int r = 0; r < 4; r++) {
            int t = r * 16 + tok;
            const float* src = qkv + (row_base + q0 + t) * QKV_N + h * HD + d4 * 4;
            float4 v = *(const float4*)src;
            Qs[(d4 * 4 + 0) * APAD + t] = v.x * scale;
            Qs[(d4 * 4 + 1) * APAD + t] = v.y * scale;
            Qs[(d4 * 4 + 2) * APAD + t] = v.z * scale;
            Qs[(d4 * 4 + 3) * APAD + t] = v.w * scale;
        }
    }

    float o[4][4];
#pragma unroll
    for (int i = 0; i < 4; i++)
#pragma unroll
        for (int j = 0; j < 4; j++) o[i][j] = 0.0f;
    float m_run[4], l_run[4];
#pragma unroll
    for (int i = 0; i < 4; i++) { m_run[i] = -INFINITY; l_run[i] = 0.0f; }

    for (int kt = 0; kt <= qt; kt++) {
        const int k0 = kt * ABN;
        {
            const int tok = tid / 16;
            const int d4  = tid % 16;
#pragma unroll
            for (int r = 0; r < 4; r++) {
                int t = r * 16 + tok;
                const float* ksrc = qkv + (row_base + k0 + t) * QKV_N + DD + h * HD + d4 * 4;
                float4 kv = *(const float4*)ksrc;
                Ks[(d4 * 4 + 0) * APAD + t] = kv.x;
                Ks[(d4 * 4 + 1) * APAD + t] = kv.y;
                Ks[(d4 * 4 + 2) * APAD + t] = kv.z;
                Ks[(d4 * 4 + 3) * APAD + t] = kv.w;
                const float* vsrc = qkv + (row_base + k0 + t) * QKV_N + 2 * DD + h * HD + d4 * 4;
                float4 vv = *(const float4*)vsrc;
                *(float4*)(&Vs[t * APAD + d4 * 4]) = vv;
            }
        }
        __syncthreads();

        float s[4][4];
#pragma unroll
        for (int i = 0; i < 4; i++)
#pragma unroll
            for (int j = 0; j < 4; j++) s[i][j] = 0.0f;

#pragma unroll 8
        for (int d = 0; d < 64; d++) {
            float4 qv = *(const float4*)(&Qs[d * APAD + tr * 4]);
            float4 kv = *(const float4*)(&Ks[d * APAD + tc * 4]);
            float qa[4] = {qv.x, qv.y, qv.z, qv.w};
            float ka[4] = {kv.x, kv.y, kv.z, kv.w};
#pragma unroll
            for (int i = 0; i < 4; i++)
#pragma unroll
                for (int j = 0; j < 4; j++)
                    s[i][j] = fmaf(qa[i], ka[j], s[i][j]);
        }

        if (kt == qt) {
#pragma unroll
            for (int i = 0; i < 4; i++) {
                int qg = q0 + tr * 4 + i;
#pragma unroll
                for (int j = 0; j < 4; j++) {
                    int kg = k0 + tc * 4 + j;
                    if (kg > qg) s[i][j] = -INFINITY;
                }
            }
        }

        float m_new[4], alpha[4];
#pragma unroll
        for (int i = 0; i < 4; i++) {
            float mx = s[i][0];
            mx = fmaxf(mx, s[i][1]); mx = fmaxf(mx, s[i][2]); mx = fmaxf(mx, s[i][3]);
#pragma unroll
            for (int w = 1; w < 16; w <<= 1)
                mx = fmaxf(mx, __shfl_xor_sync(0xffffffffu, mx, w));
            m_new[i] = fmaxf(m_run[i], mx);
        }
#pragma unroll
        for (int i = 0; i < 4; i++) {
            float rs = 0.0f;
#pragma unroll
            for (int j = 0; j < 4; j++) {
                float p = __expf(s[i][j] - m_new[i]);
                s[i][j] = p;
                rs += p;
            }
#pragma unroll
            for (int w = 1; w < 16; w <<= 1)
                rs += __shfl_xor_sync(0xffffffffu, rs, w);
            alpha[i] = __expf(m_run[i] - m_new[i]);
            l_run[i] = l_run[i] * alpha[i] + rs;
            m_run[i] = m_new[i];
#pragma unroll
            for (int j = 0; j < 4; j++) o[i][j] *= alpha[i];
        }

#pragma unroll
        for (int i = 0; i < 4; i++)
#pragma unroll
            for (int j = 0; j < 4; j++)
                Ps[(tc * 4 + j) * APAD + (tr * 4 + i)] = s[i][j];
        __syncthreads();

#pragma unroll 8
        for (int kk = 0; kk < 64; kk++) {
            float4 pv = *(const float4*)(&Ps[kk * APAD + tr * 4]);
            float4 vv = *(const float4*)(&Vs[kk * APAD + tc * 4]);
            float pa[4] = {pv.x, pv.y, pv.z, pv.w};
            float va[4] = {vv.x, vv.y, vv.z, vv.w};
#pragma unroll
            for (int i = 0; i < 4; i++)
#pragma unroll
                for (int j = 0; j < 4; j++)
                    o[i][j] = fmaf(pa[i], va[j], o[i][j]);
        }
        __syncthreads();
    }

    // Epilogue: normalize, split to bf16 hi/lo, store
#pragma unroll
    for (int i = 0; i < 4; i++) {
        float inv_l = 1.0f / l_run[i];
        size_t row = row_base + q0 + tr * 4 + i;
        float v0 = o[i][0] * inv_l, v1 = o[i][1] * inv_l;
        float v2 = o[i][2] * inv_l, v3 = o[i][3] * inv_l;
        uint32_t h0, l0, h1, l1;
        split_pack(v0, v1, h0, l0);
        split_pack(v2, v3, h1, l1);
        size_t off = row * DD + h * HD + tc * 4;
        *(uint2*)(aoh + off) = make_uint2(h0, h1);
        *(uint2*)(aol + off) = make_uint2(l0, l1);
    }
}

// ---------------------------------------------------------------------------
// Launch
// ---------------------------------------------------------------------------
extern "C" void kernel_launch(void* const* d_in, const int* in_sizes, int n_in,
                              void* d_out, int out_size) {
    const float* x      = (const float*)d_in[0];
    const float* W_attn = (const float*)d_in[1];
    const float* b_attn = (const float*)d_in[2];
    const float* W_proj = (const float*)d_in[3];
    const float* b_proj = (const float*)d_in[4];
    float* out = (float*)d_out;

    float* qkv = nullptr;
    __nv_bfloat16 *xh, *xl, *aoh, *aol, *wah, *wal, *wph, *wpl;
    cudaGetSymbolAddress((void**)&qkv, g_qkv);
    cudaGetSymbolAddress((void**)&xh, g_xh);
    cudaGetSymbolAddress((void**)&xl, g_xl);
    cudaGetSymbolAddress((void**)&aoh, g_aoh);
    cudaGetSymbolAddress((void**)&aol, g_aol);
    cudaGetSymbolAddress((void**)&wah, g_wah);
    cudaGetSymbolAddress((void**)&wal, g_wal);
    cudaGetSymbolAddress((void**)&wph, g_wph);
    cudaGetSymbolAddress((void**)&wpl, g_wpl);

    static const size_t flash_smem = ASM_FLOATS * sizeof(float);
    cudaFuncSetAttribute(flash_attn_kernel,
                         cudaFuncAttributeMaxDynamicSharedMemorySize, (int)flash_smem);
    cudaFuncSetAttribute(gemm_bf16_kernel,
                         cudaFuncAttributeMaxDynamicSharedMemorySize, GEMM_SMEM);

    // 0) Pre-split inputs
    split_kernel<<<(ROWS * DD / 4) / 256, 256>>>((const float4*)x, (uint2*)xh, (uint2*)xl,
                                                 ROWS * DD / 4);
    split_wT_kernel<<<dim3(QKV_N / 32, DD / 32), dim3(32, 8)>>>(W_attn, wah, wal, DD, QKV_N);
    split_wT_kernel<<<dim3(DD / 32, DD / 32), dim3(32, 8)>>>(W_proj, wph, wpl, DD, DD);

    // 1) QKV projection: [8192,3072] = x @ W_attn + b_attn
    {
        dim3 grid(QKV_N / 128, ROWS / 128);
        gemm_bf16_kernel<<<grid, 256, GEMM_SMEM>>>(xh, xl, wah, wal, b_attn, qkv, QKV_N, DD);
    }
    // 2) Flash attention (writes split bf16 output)
    {
        dim3 grid(SS / ABM, HH, BB);
        flash_attn_kernel<<<grid, 256, flash_smem>>>(qkv, aoh, aol);
    }
    // 3) Output projection: out = attn_out @ W_proj + b_proj
    {
        dim3 grid(DD / 128, ROWS / 128);
        gemm_bf16_kernel<<<grid, 256, GEMM_SMEM>>>(aoh, aol, wph, wpl, b_proj, out, DD, DD);
    }
}

// round 6
// speedup vs baseline: 2.5225x; 1.5932x over previous
#include <cuda_runtime.h>
#include <cuda_bf16.h>
#include <math.h>
#include <stdint.h>

// Problem constants
#define BB 4
#define SS 2048
#define DD 1024
#define HH 16
#define HD 64
#define ROWS (BB * SS)        // 8192
#define QKV_N (3 * DD)        // 3072

// Scratch (allocation-free rule: __device__ globals)
__device__ __align__(16) __nv_bfloat16 g_qkvh[ROWS * QKV_N]; // qkv split hi
__device__ __align__(16) __nv_bfloat16 g_qkvl[ROWS * QKV_N]; // qkv split lo
__device__ __align__(16) __nv_bfloat16 g_xh[ROWS * DD];
__device__ __align__(16) __nv_bfloat16 g_xl[ROWS * DD];
__device__ __align__(16) __nv_bfloat16 g_aoh[ROWS * DD];
__device__ __align__(16) __nv_bfloat16 g_aol[ROWS * DD];
__device__ __align__(16) __nv_bfloat16 g_wah[QKV_N * DD];
__device__ __align__(16) __nv_bfloat16 g_wal[QKV_N * DD];
__device__ __align__(16) __nv_bfloat16 g_wph[DD * DD];
__device__ __align__(16) __nv_bfloat16 g_wpl[DD * DD];

__device__ __forceinline__ uint32_t smem_u32(const void* p) {
    uint32_t a;
    asm("{ .reg .u64 t; cvta.to.shared.u64 t, %1; cvt.u32.u64 %0, t; }" : "=r"(a) : "l"(p));
    return a;
}

__device__ __forceinline__ void split_pack(float x, float y, uint32_t& h, uint32_t& l) {
    __nv_bfloat16 hx = __float2bfloat16(x), hy = __float2bfloat16(y);
    float rx = x - __bfloat162float(hx);
    float ry = y - __bfloat162float(hy);
    __nv_bfloat16 lx = __float2bfloat16(rx), ly = __float2bfloat16(ry);
    h = ((uint32_t)__bfloat16_as_ushort(hy) << 16) | (uint32_t)__bfloat16_as_ushort(hx);
    l = ((uint32_t)__bfloat16_as_ushort(ly) << 16) | (uint32_t)__bfloat16_as_ushort(lx);
}

#define LDMATRIX_X4(r0, r1, r2, r3, addr) \
    asm volatile("ldmatrix.sync.aligned.m8n8.x4.shared.b16 {%0,%1,%2,%3}, [%4];" \
        : "=r"(r0), "=r"(r1), "=r"(r2), "=r"(r3) : "r"(addr))

#define LDMATRIX_X4_T(r0, r1, r2, r3, addr) \
    asm volatile("ldmatrix.sync.aligned.m8n8.x4.trans.shared.b16 {%0,%1,%2,%3}, [%4];" \
        : "=r"(r0), "=r"(r1), "=r"(r2), "=r"(r3) : "r"(addr))

#define MMA_BF16(d, a, b) \
    asm volatile("mma.sync.aligned.m16n8k16.row.col.f32.bf16.bf16.f32 " \
        "{%0,%1,%2,%3}, {%4,%5,%6,%7}, {%8,%9}, {%0,%1,%2,%3};" \
        : "+f"((d)[0]), "+f"((d)[1]), "+f"((d)[2]), "+f"((d)[3]) \
        : "r"((a)[0]), "r"((a)[1]), "r"((a)[2]), "r"((a)[3]), \
          "r"((b)[0]), "r"((b)[1]))

#define CP16(dst, src) \
    asm volatile("cp.async.cg.shared.global [%0], [%1], 16;" :: "r"(dst), "l"(src))
#define CP_COMMIT() asm volatile("cp.async.commit_group;")
#define CP_WAIT0()  asm volatile("cp.async.wait_group 0;" ::: "memory")
#define CP_WAIT1()  asm volatile("cp.async.wait_group 1;" ::: "memory")

// ---------------------------------------------------------------------------
// Pre-split kernels
// ---------------------------------------------------------------------------
__global__ void split_kernel(const float4* __restrict__ src,
                             uint2* __restrict__ hi, uint2* __restrict__ lo, int n4) {
    int i = blockIdx.x * 256 + threadIdx.x;
    if (i >= n4) return;
    float4 v = src[i];
    uint32_t h0, l0, h1, l1;
    split_pack(v.x, v.y, h0, l0);
    split_pack(v.z, v.w, h1, l1);
    hi[i] = make_uint2(h0, h1);
    lo[i] = make_uint2(l0, l1);
}

__global__ void split_wT_kernel(const float* __restrict__ W,
                                __nv_bfloat16* __restrict__ Wh,
                                __nv_bfloat16* __restrict__ Wl, int K, int N) {
    __shared__ float t[32][33];
    const int n0 = blockIdx.x * 32, k0 = blockIdx.y * 32;
    const int tx = threadIdx.x, ty = threadIdx.y;
#pragma unroll
    for (int j = 0; j < 32; j += 8)
        t[ty + j][tx] = W[(size_t)(k0 + ty + j) * N + n0 + tx];
    __syncthreads();
#pragma unroll
    for (int j = 0; j < 32; j += 8) {
        float v = t[tx][ty + j];
        __nv_bfloat16 h = __float2bfloat16(v);
        __nv_bfloat16 l = __float2bfloat16(v - __bfloat162float(h));
        size_t o = (size_t)(n0 + ty + j) * K + k0 + tx;
        Wh[o] = h;
        Wl[o] = l;
    }
}

// ---------------------------------------------------------------------------
// bf16-split GEMM (cp.async double buffer). Optional split-bf16 output.
// ---------------------------------------------------------------------------
#define GSTRIDE 80
#define STG_A_HI 0
#define STG_A_LO 10240
#define STG_B_HI 20480
#define STG_B_LO 30720
#define STAGE_BYTES 40960
#define GEMM_SMEM (2 * STAGE_BYTES)

__global__ void __launch_bounds__(256, 2)
gemm_bf16_kernel(const __nv_bfloat16* __restrict__ Ah, const __nv_bfloat16* __restrict__ Al,
                 const __nv_bfloat16* __restrict__ Bh, const __nv_bfloat16* __restrict__ Bl,
                 const float* __restrict__ bias, float* __restrict__ C,
                 __nv_bfloat16* __restrict__ Ch, __nv_bfloat16* __restrict__ Cl,
                 int N, int K) {
    extern __shared__ __align__(16) unsigned char smem[];
    const uint32_t sb = smem_u32(smem);

    const int tid = threadIdx.x;
    const int wid = tid >> 5;
    const int lid = tid & 31;
    const int warp_m = wid & 3;
    const int warp_n = wid >> 2;

    const int m0 = blockIdx.y * 128;
    const int n0 = blockIdx.x * 128;

    const int fr = tid >> 2;
    const int seg = tid & 3;

    const __nv_bfloat16* a_h = Ah + (size_t)(m0 + fr) * K + seg * 8;
    const __nv_bfloat16* a_l = Al + (size_t)(m0 + fr) * K + seg * 8;
    const __nv_bfloat16* b_h = Bh + (size_t)(n0 + fr) * K + seg * 8;
    const __nv_bfloat16* b_l = Bl + (size_t)(n0 + fr) * K + seg * 8;

    float acc[2][8][4];
#pragma unroll
    for (int i = 0; i < 2; i++)
#pragma unroll
        for (int j = 0; j < 8; j++)
#pragma unroll
            for (int v = 0; v < 4; v++) acc[i][j][v] = 0.0f;

    const uint32_t a_lane_row = (uint32_t)(warp_m * 32 + (lid & 15));
    const uint32_t a_lane_kb = (uint32_t)((lid >> 4) * 16);
    const uint32_t b_lane_row = (uint32_t)(warp_n * 64 + (lid & 7) + ((lid >> 4) & 1) * 8);
    const uint32_t b_lane_kb = (uint32_t)(((lid >> 3) & 1) * 16);

    const uint32_t doff = (uint32_t)(fr * GSTRIDE + seg * 16);

    auto fill = [&](int s, int kc) {
        const uint32_t base = sb + s * STAGE_BYTES;
        const size_t ko = (size_t)kc * 32;
        CP16(base + STG_A_HI + doff, a_h + ko);
        CP16(base + STG_A_HI + doff + 64 * GSTRIDE, a_h + ko + (size_t)64 * K);
        CP16(base + STG_A_LO + doff, a_l + ko);
        CP16(base + STG_A_LO + doff + 64 * GSTRIDE, a_l + ko + (size_t)64 * K);
        CP16(base + STG_B_HI + doff, b_h + ko);
        CP16(base + STG_B_HI + doff + 64 * GSTRIDE, b_h + ko + (size_t)64 * K);
        CP16(base + STG_B_LO + doff, b_l + ko);
        CP16(base + STG_B_LO + doff + 64 * GSTRIDE, b_l + ko + (size_t)64 * K);
    };

    auto do_mma = [&](int s) {
        const uint32_t base = sb + s * STAGE_BYTES;
#pragma unroll
        for (int ks = 0; ks < 2; ks++) {
            uint32_t ah[2][4], al[2][4];
#pragma unroll
            for (int mt = 0; mt < 2; mt++) {
                uint32_t addr = base + STG_A_HI +
                    (a_lane_row + mt * 16) * GSTRIDE + ks * 32 + a_lane_kb;
                LDMATRIX_X4(ah[mt][0], ah[mt][1], ah[mt][2], ah[mt][3], addr);
                LDMATRIX_X4(al[mt][0], al[mt][1], al[mt][2], al[mt][3],
                            addr + (STG_A_LO - STG_A_HI));
            }
#pragma unroll
            for (int pb = 0; pb < 4; pb++) {
                uint32_t bh0[2], bh1[2], bl0[2], bl1[2];
                uint32_t addr = base + STG_B_HI +
                    (b_lane_row + pb * 16) * GSTRIDE + ks * 32 + b_lane_kb;
                LDMATRIX_X4(bh0[0], bh0[1], bh1[0], bh1[1], addr);
                LDMATRIX_X4(bl0[0], bl0[1], bl1[0], bl1[1],
                            addr + (STG_B_LO - STG_B_HI));
#pragma unroll
                for (int mt = 0; mt < 2; mt++) {
                    MMA_BF16(acc[mt][2 * pb], ah[mt], bh0);
                    MMA_BF16(acc[mt][2 * pb], ah[mt], bl0);
                    MMA_BF16(acc[mt][2 * pb], al[mt], bh0);
                    MMA_BF16(acc[mt][2 * pb + 1], ah[mt], bh1);
                    MMA_BF16(acc[mt][2 * pb + 1], ah[mt], bl1);
                    MMA_BF16(acc[mt][2 * pb + 1], al[mt], bh1);
                }
            }
        }
    };

    const int nchunks = K >> 5;
    fill(0, 0);
    CP_COMMIT();

    for (int kc = 0; kc < nchunks; kc++) {
        CP_WAIT0();
        __syncthreads();
        if (kc + 1 < nchunks) {
            fill((kc + 1) & 1, kc + 1);
            CP_COMMIT();
        }
        do_mma(kc & 1);
        __syncthreads();
    }

#pragma unroll
    for (int mt = 0; mt < 2; mt++) {
        int r0 = m0 + warp_m * 32 + mt * 16 + (lid >> 2);
#pragma unroll
        for (int nt = 0; nt < 8; nt++) {
            int col = n0 + warp_n * 64 + nt * 8 + (lid & 3) * 2;
            float2 bv = *(const float2*)(bias + col);
            float c0x = acc[mt][nt][0] + bv.x, c0y = acc[mt][nt][1] + bv.y;
            float c1x = acc[mt][nt][2] + bv.x, c1y = acc[mt][nt][3] + bv.y;
            if (Ch) {
                uint32_t h0, l0, h1, l1;
                split_pack(c0x, c0y, h0, l0);
                split_pack(c1x, c1y, h1, l1);
                *(uint32_t*)(Ch + (size_t)r0 * N + col) = h0;
                *(uint32_t*)(Cl + (size_t)r0 * N + col) = l0;
                *(uint32_t*)(Ch + (size_t)(r0 + 8) * N + col) = h1;
                *(uint32_t*)(Cl + (size_t)(r0 + 8) * N + col) = l1;
            } else {
                *(float2*)(C + (size_t)r0 * N + col) = make_float2(c0x, c0y);
                *(float2*)(C + (size_t)(r0 + 8) * N + col) = make_float2(c1x, c1y);
            }
        }
    }
}

// ---------------------------------------------------------------------------
// Tensor-core flash attention (bf16-split, causal).
// 64 q-rows per CTA, 4 warps x 16 rows. K-tiles of 64, cp.async double buffer.
// Q/K: natural [row][d] layout; V consumed via ldmatrix.trans.
// ---------------------------------------------------------------------------
#define FSTR 144                 // 64 bf16 (128B) + 16B pad per row
#define F_QH 0
#define F_QL 9216
#define F_STAGE0 18432
#define F_STAGE_BYTES 36864
#define F_KH 0
#define F_KL 9216
#define F_VH 18432
#define F_VL 27648
#define FLASH_SMEM (F_STAGE0 + 2 * F_STAGE_BYTES)   // 92160

__global__ void __launch_bounds__(128)
flash_attn_tc_kernel(const __nv_bfloat16* __restrict__ qkvh,
                     const __nv_bfloat16* __restrict__ qkvl,
                     __nv_bfloat16* __restrict__ aoh,
                     __nv_bfloat16* __restrict__ aol) {
    extern __shared__ __align__(16) unsigned char smem[];
    const uint32_t sb = smem_u32(smem);

    const int qt = blockIdx.x;
    const int h  = blockIdx.y;
    const int b  = blockIdx.z;
    const int tid = threadIdx.x;
    const int w = tid >> 5;
    const int l = tid & 31;
    const int g = l >> 2;
    const int t = l & 3;
    const int w16 = w * 16;

    const int q0 = qt * 64;
    const size_t rb = (size_t)b * SS;

    // Fill indexing
    const int ft = tid >> 1;    // row 0..63
    const int fseg = tid & 1;   // half-row (64B)

    const __nv_bfloat16* qh_src = qkvh + (rb + q0 + ft) * (size_t)QKV_N + h * HD + fseg * 32;
    const __nv_bfloat16* ql_src = qkvl + (rb + q0 + ft) * (size_t)QKV_N + h * HD + fseg * 32;

    // Load Q (group 0)
    {
        uint32_t dq = sb + F_QH + ft * FSTR + fseg * 64;
#pragma unroll
        for (int j = 0; j < 4; j++) {
            CP16(dq + j * 16, qh_src + j * 8);
            CP16(dq + (F_QL - F_QH) + j * 16, ql_src + j * 8);
        }
    }

    auto fillKV = [&](int s, int kt) {
        const uint32_t base = sb + F_STAGE0 + s * F_STAGE_BYTES;
        const size_t row = rb + (size_t)kt * 64 + ft;
        const __nv_bfloat16* kh = qkvh + row * QKV_N + DD + h * HD + fseg * 32;
        const __nv_bfloat16* kl = qkvl + row * QKV_N + DD + h * HD + fseg * 32;
        const __nv_bfloat16* vh = qkvh + row * QKV_N + 2 * DD + h * HD + fseg * 32;
        const __nv_bfloat16* vl = qkvl + row * QKV_N + 2 * DD + h * HD + fseg * 32;
        const uint32_t d = ft * FSTR + fseg * 64;
#pragma unroll
        for (int j = 0; j < 4; j++) {
            CP16(base + F_KH + d + j * 16, kh + j * 8);
            CP16(base + F_KL + d + j * 16, kl + j * 8);
            CP16(base + F_VH + d + j * 16, vh + j * 8);
            CP16(base + F_VL + d + j * 16, vl + j * 8);
        }
    };

    fillKV(0, 0);
    CP_COMMIT();

    float o[8][4];
#pragma unroll
    for (int j = 0; j < 8; j++)
#pragma unroll
        for (int v = 0; v < 4; v++) o[j][v] = 0.0f;
    float m0 = -INFINITY, m1 = -INFINITY, l0 = 0.0f, l1 = 0.0f;

    // ldmatrix lane addresses
    const uint32_t a_row = (uint32_t)(w16 + (l & 15));
    const uint32_t a_kb = (uint32_t)((l >> 4) * 16);
    const uint32_t b_row = (uint32_t)((l & 7) + ((l >> 4) & 1) * 8);
    const uint32_t b_kb = (uint32_t)(((l >> 3) & 1) * 16);
    const uint32_t v_row = (uint32_t)(l & 15);
    const uint32_t v_cb = (uint32_t)((l >> 4) * 16);

    const float sc = 0.125f;

    for (int kt = 0; kt <= qt; kt++) {
        __syncthreads();
        if (kt + 1 <= qt) {
            fillKV((kt + 1) & 1, kt + 1);
            CP_COMMIT();
            CP_WAIT1();
        } else {
            CP_WAIT0();
        }
        __syncthreads();

        const uint32_t stg = sb + F_STAGE0 + (kt & 1) * F_STAGE_BYTES;

        // ---- S = Q K^T (split, 3 terms) ----
        float s_[8][4];
#pragma unroll
        for (int j = 0; j < 8; j++)
#pragma unroll
            for (int v = 0; v < 4; v++) s_[j][v] = 0.0f;

#pragma unroll
        for (int ks = 0; ks < 4; ks++) {
            uint32_t qh[4], ql[4];
            uint32_t qaddr = sb + F_QH + a_row * FSTR + ks * 32 + a_kb;
            LDMATRIX_X4(qh[0], qh[1], qh[2], qh[3], qaddr);
            LDMATRIX_X4(ql[0], ql[1], ql[2], ql[3], qaddr + (F_QL - F_QH));
#pragma unroll
            for (int pb = 0; pb < 4; pb++) {
                uint32_t kh0[2], kh1[2], kl0[2], kl1[2];
                uint32_t kaddr = stg + F_KH + (b_row + pb * 16) * FSTR + ks * 32 + b_kb;
                LDMATRIX_X4(kh0[0], kh0[1], kh1[0], kh1[1], kaddr);
                LDMATRIX_X4(kl0[0], kl0[1], kl1[0], kl1[1], kaddr + (F_KL - F_KH));
                MMA_BF16(s_[2 * pb], qh, kh0);
                MMA_BF16(s_[2 * pb], qh, kl0);
                MMA_BF16(s_[2 * pb], ql, kh0);
                MMA_BF16(s_[2 * pb + 1], qh, kh1);
                MMA_BF16(s_[2 * pb + 1], qh, kl1);
                MMA_BF16(s_[2 * pb + 1], ql, kh1);
            }
        }

        // ---- scale + causal mask ----
#pragma unroll
        for (int j = 0; j < 8; j++)
#pragma unroll
            for (int v = 0; v < 4; v++) s_[j][v] *= sc;

        if (kt == qt) {
            const int lr0 = w16 + g, lr1 = lr0 + 8;
#pragma unroll
            for (int j = 0; j < 8; j++) {
                int lc = 8 * j + 2 * t;
                if (lc > lr0) s_[j][0] = -INFINITY;
                if (lc + 1 > lr0) s_[j][1] = -INFINITY;
                if (lc > lr1) s_[j][2] = -INFINITY;
                if (lc + 1 > lr1) s_[j][3] = -INFINITY;
            }
        }

        // ---- online softmax ----
        float tm0 = -INFINITY, tm1 = -INFINITY;
#pragma unroll
        for (int j = 0; j < 8; j++) {
            tm0 = fmaxf(tm0, fmaxf(s_[j][0], s_[j][1]));
            tm1 = fmaxf(tm1, fmaxf(s_[j][2], s_[j][3]));
        }
        tm0 = fmaxf(tm0, __shfl_xor_sync(0xffffffffu, tm0, 1));
        tm0 = fmaxf(tm0, __shfl_xor_sync(0xffffffffu, tm0, 2));
        tm1 = fmaxf(tm1, __shfl_xor_sync(0xffffffffu, tm1, 1));
        tm1 = fmaxf(tm1, __shfl_xor_sync(0xffffffffu, tm1, 2));

        float mn0 = fmaxf(m0, tm0), mn1 = fmaxf(m1, tm1);
        float alpha0 = __expf(m0 - mn0), alpha1 = __expf(m1 - mn1);
        float rs0 = 0.0f, rs1 = 0.0f;
#pragma unroll
        for (int j = 0; j < 8; j++) {
            s_[j][0] = __expf(s_[j][0] - mn0);
            s_[j][1] = __expf(s_[j][1] - mn0);
            s_[j][2] = __expf(s_[j][2] - mn1);
            s_[j][3] = __expf(s_[j][3] - mn1);
            rs0 += s_[j][0] + s_[j][1];
            rs1 += s_[j][2] + s_[j][3];
        }
        rs0 += __shfl_xor_sync(0xffffffffu, rs0, 1);
        rs0 += __shfl_xor_sync(0xffffffffu, rs0, 2);
        rs1 += __shfl_xor_sync(0xffffffffu, rs1, 1);
        rs1 += __shfl_xor_sync(0xffffffffu, rs1, 2);
        l0 = l0 * alpha0 + rs0;
        l1 = l1 * alpha1 + rs1;
        m0 = mn0;
        m1 = mn1;
#pragma unroll
        for (int j = 0; j < 8; j++) {
            o[j][0] *= alpha0;
            o[j][1] *= alpha0;
            o[j][2] *= alpha1;
            o[j][3] *= alpha1;
        }

        // ---- O += P V (split P hi/lo in-register, V via ldmatrix.trans) ----
#pragma unroll
        for (int s = 0; s < 4; s++) {
            uint32_t ph[4], pl[4];
            split_pack(s_[2 * s][0], s_[2 * s][1], ph[0], pl[0]);
            split_pack(s_[2 * s][2], s_[2 * s][3], ph[1], pl[1]);
            split_pack(s_[2 * s + 1][0], s_[2 * s + 1][1], ph[2], pl[2]);
            split_pack(s_[2 * s + 1][2], s_[2 * s + 1][3], ph[3], pl[3]);
#pragma unroll
            for (int jp = 0; jp < 4; jp++) {
                uint32_t vh[4], vl[4];
                uint32_t vaddr = stg + F_VH + (16 * s + v_row) * FSTR + jp * 32 + v_cb;
                LDMATRIX_X4_T(vh[0], vh[1], vh[2], vh[3], vaddr);
                LDMATRIX_X4_T(vl[0], vl[1], vl[2], vl[3], vaddr + (F_VL - F_VH));
                uint32_t bh0[2] = {vh[0], vh[1]}, bh1[2] = {vh[2], vh[3]};
                uint32_t bl0[2] = {vl[0], vl[1]}, bl1[2] = {vl[2], vl[3]};
                MMA_BF16(o[2 * jp], ph, bh0);
                MMA_BF16(o[2 * jp], ph, bl0);
                MMA_BF16(o[2 * jp], pl, bh0);
                MMA_BF16(o[2 * jp + 1], ph, bh1);
                MMA_BF16(o[2 * jp + 1], ph, bl1);
                MMA_BF16(o[2 * jp + 1], pl, bh1);
            }
        }
    }

    // ---- epilogue: normalize, split, store ----
    const float inv0 = 1.0f / l0, inv1 = 1.0f / l1;
    const size_t r0 = rb + q0 + w16 + g;
    const size_t r1 = r0 + 8;
#pragma unroll
    for (int j = 0; j < 8; j++) {
        int c = h * HD + 8 * j + 2 * t;
        uint32_t h0, lo0, h1, lo1;
        split_pack(o[j][0] * inv0, o[j][1] * inv0, h0, lo0);
        split_pack(o[j][2] * inv1, o[j][3] * inv1, h1, lo1);
        *(uint32_t*)(aoh + r0 * DD + c) = h0;
        *(uint32_t*)(aol + r0 * DD + c) = lo0;
        *(uint32_t*)(aoh + r1 * DD + c) = h1;
        *(uint32_t*)(aol + r1 * DD + c) = lo1;
    }
}

// ---------------------------------------------------------------------------
// Launch
// ---------------------------------------------------------------------------
extern "C" void kernel_launch(void* const* d_in, const int* in_sizes, int n_in,
                              void* d_out, int out_size) {
    const float* x      = (const float*)d_in[0];
    const float* W_attn = (const float*)d_in[1];
    const float* b_attn = (const float*)d_in[2];
    const float* W_proj = (const float*)d_in[3];
    const float* b_proj = (const float*)d_in[4];
    float* out = (float*)d_out;

    __nv_bfloat16 *qkvh, *qkvl, *xh, *xl, *aoh, *aol, *wah, *wal, *wph, *wpl;
    cudaGetSymbolAddress((void**)&qkvh, g_qkvh);
    cudaGetSymbolAddress((void**)&qkvl, g_qkvl);
    cudaGetSymbolAddress((void**)&xh, g_xh);
    cudaGetSymbolAddress((void**)&xl, g_xl);
    cudaGetSymbolAddress((void**)&aoh, g_aoh);
    cudaGetSymbolAddress((void**)&aol, g_aol);
    cudaGetSymbolAddress((void**)&wah, g_wah);
    cudaGetSymbolAddress((void**)&wal, g_wal);
    cudaGetSymbolAddress((void**)&wph, g_wph);
    cudaGetSymbolAddress((void**)&wpl, g_wpl);

    cudaFuncSetAttribute(gemm_bf16_kernel,
                         cudaFuncAttributeMaxDynamicSharedMemorySize, GEMM_SMEM);
    cudaFuncSetAttribute(flash_attn_tc_kernel,
                         cudaFuncAttributeMaxDynamicSharedMemorySize, FLASH_SMEM);

    // 0) Pre-split inputs
    split_kernel<<<(ROWS * DD / 4) / 256, 256>>>((const float4*)x, (uint2*)xh, (uint2*)xl,
                                                 ROWS * DD / 4);
    split_wT_kernel<<<dim3(QKV_N / 32, DD / 32), dim3(32, 8)>>>(W_attn, wah, wal, DD, QKV_N);
    split_wT_kernel<<<dim3(DD / 32, DD / 32), dim3(32, 8)>>>(W_proj, wph, wpl, DD, DD);

    // 1) QKV projection -> split bf16 output
    {
        dim3 grid(QKV_N / 128, ROWS / 128);
        gemm_bf16_kernel<<<grid, 256, GEMM_SMEM>>>(xh, xl, wah, wal, b_attn,
                                                   nullptr, qkvh, qkvl, QKV_N, DD);
    }
    // 2) Tensor-core flash attention
    {
        dim3 grid(SS / 64, HH, BB);
        flash_attn_tc_kernel<<<grid, 128, FLASH_SMEM>>>(qkvh, qkvl, aoh, aol);
    }
    // 3) Output projection -> fp32 out
    {
        dim3 grid(DD / 128, ROWS / 128);
        gemm_bf16_kernel<<<grid, 256, GEMM_SMEM>>>(aoh, aol, wph, wpl, b_proj,
                                                   out, nullptr, nullptr, DD, DD);
    }
}

// round 9
// speedup vs baseline: 2.7867x; 1.1047x over previous
#include <cuda_runtime.h>
#include <cuda_bf16.h>
#include <math.h>
#include <stdint.h>

// Problem constants
#define BB 4
#define SS 2048
#define DD 1024
#define HH 16
#define HD 64
#define ROWS (BB * SS)        // 8192
#define QKV_N (3 * DD)        // 3072

// Scratch (allocation-free rule: __device__ globals)
__device__ __align__(16) __nv_bfloat16 g_qkvh[ROWS * QKV_N]; // qkv split hi
__device__ __align__(16) __nv_bfloat16 g_qkvl[ROWS * QKV_N]; // qkv split lo
__device__ __align__(16) __nv_bfloat16 g_xh[ROWS * DD];
__device__ __align__(16) __nv_bfloat16 g_xl[ROWS * DD];
__device__ __align__(16) __nv_bfloat16 g_aoh[ROWS * DD];
__device__ __align__(16) __nv_bfloat16 g_aol[ROWS * DD];
__device__ __align__(16) __nv_bfloat16 g_wah[QKV_N * DD];
__device__ __align__(16) __nv_bfloat16 g_wal[QKV_N * DD];
__device__ __align__(16) __nv_bfloat16 g_wph[DD * DD];
__device__ __align__(16) __nv_bfloat16 g_wpl[DD * DD];

__device__ __forceinline__ uint32_t smem_u32(const void* p) {
    uint32_t a;
    asm("{ .reg .u64 t; cvta.to.shared.u64 t, %1; cvt.u32.u64 %0, t; }" : "=r"(a) : "l"(p));
    return a;
}

__device__ __forceinline__ void split_pack(float x, float y, uint32_t& h, uint32_t& l) {
    __nv_bfloat16 hx = __float2bfloat16(x), hy = __float2bfloat16(y);
    float rx = x - __bfloat162float(hx);
    float ry = y - __bfloat162float(hy);
    __nv_bfloat16 lx = __float2bfloat16(rx), ly = __float2bfloat16(ry);
    h = ((uint32_t)__bfloat16_as_ushort(hy) << 16) | (uint32_t)__bfloat16_as_ushort(hx);
    l = ((uint32_t)__bfloat16_as_ushort(ly) << 16) | (uint32_t)__bfloat16_as_ushort(lx);
}

#define LDMATRIX_X4(r0, r1, r2, r3, addr) \
    asm volatile("ldmatrix.sync.aligned.m8n8.x4.shared.b16 {%0,%1,%2,%3}, [%4];" \
        : "=r"(r0), "=r"(r1), "=r"(r2), "=r"(r3) : "r"(addr))

#define LDMATRIX_X4_T(r0, r1, r2, r3, addr) \
    asm volatile("ldmatrix.sync.aligned.m8n8.x4.trans.shared.b16 {%0,%1,%2,%3}, [%4];" \
        : "=r"(r0), "=r"(r1), "=r"(r2), "=r"(r3) : "r"(addr))

#define MMA_BF16(d, a, b) \
    asm volatile("mma.sync.aligned.m16n8k16.row.col.f32.bf16.bf16.f32 " \
        "{%0,%1,%2,%3}, {%4,%5,%6,%7}, {%8,%9}, {%0,%1,%2,%3};" \
        : "+f"((d)[0]), "+f"((d)[1]), "+f"((d)[2]), "+f"((d)[3]) \
        : "r"((a)[0]), "r"((a)[1]), "r"((a)[2]), "r"((a)[3]), \
          "r"((b)[0]), "r"((b)[1]))

#define CP16(dst, src) \
    asm volatile("cp.async.cg.shared.global [%0], [%1], 16;" :: "r"(dst), "l"(src))
#define CP_COMMIT() asm volatile("cp.async.commit_group;")
#define CP_WAIT0()  asm volatile("cp.async.wait_group 0;" ::: "memory")
#define CP_WAIT1()  asm volatile("cp.async.wait_group 1;" ::: "memory")

// ---------------------------------------------------------------------------
// Pre-split kernels
// ---------------------------------------------------------------------------
__global__ void split_kernel(const float4* __restrict__ src,
                             uint2* __restrict__ hi, uint2* __restrict__ lo, int n4) {
    int i = blockIdx.x * 256 + threadIdx.x;
    if (i >= n4) return;
    float4 v = src[i];
    uint32_t h0, l0, h1, l1;
    split_pack(v.x, v.y, h0, l0);
    split_pack(v.z, v.w, h1, l1);
    hi[i] = make_uint2(h0, h1);
    lo[i] = make_uint2(l0, l1);
}

__global__ void split_wT_kernel(const float* __restrict__ W,
                                __nv_bfloat16* __restrict__ Wh,
                                __nv_bfloat16* __restrict__ Wl, int K, int N) {
    __shared__ float t[32][33];
    const int n0 = blockIdx.x * 32, k0 = blockIdx.y * 32;
    const int tx = threadIdx.x, ty = threadIdx.y;
#pragma unroll
    for (int j = 0; j < 32; j += 8)
        t[ty + j][tx] = W[(size_t)(k0 + ty + j) * N + n0 + tx];
    __syncthreads();
#pragma unroll
    for (int j = 0; j < 32; j += 8) {
        float v = t[tx][ty + j];
        __nv_bfloat16 h = __float2bfloat16(v);
        __nv_bfloat16 l = __float2bfloat16(v - __bfloat162float(h));
        size_t o = (size_t)(n0 + ty + j) * K + k0 + tx;
        Wh[o] = h;
        Wl[o] = l;
    }
}

// ---------------------------------------------------------------------------
// bf16-split GEMM (cp.async double buffer). Optional split-bf16 output.
// ---------------------------------------------------------------------------
#define GSTRIDE 80
#define STG_A_HI 0
#define STG_A_LO 10240
#define STG_B_HI 20480
#define STG_B_LO 30720
#define STAGE_BYTES 40960
#define GEMM_SMEM (2 * STAGE_BYTES)

__global__ void __launch_bounds__(256, 2)
gemm_bf16_kernel(const __nv_bfloat16* __restrict__ Ah, const __nv_bfloat16* __restrict__ Al,
                 const __nv_bfloat16* __restrict__ Bh, const __nv_bfloat16* __restrict__ Bl,
                 const float* __restrict__ bias, float* __restrict__ C,
                 __nv_bfloat16* __restrict__ Ch, __nv_bfloat16* __restrict__ Cl,
                 int N, int K) {
    extern __shared__ __align__(16) unsigned char smem[];
    const uint32_t sb = smem_u32(smem);

    const int tid = threadIdx.x;
    const int wid = tid >> 5;
    const int lid = tid & 31;
    const int warp_m = wid & 3;
    const int warp_n = wid >> 2;

    const int m0 = blockIdx.y * 128;
    const int n0 = blockIdx.x * 128;

    const int fr = tid >> 2;
    const int seg = tid & 3;

    const __nv_bfloat16* a_h = Ah + (size_t)(m0 + fr) * K + seg * 8;
    const __nv_bfloat16* a_l = Al + (size_t)(m0 + fr) * K + seg * 8;
    const __nv_bfloat16* b_h = Bh + (size_t)(n0 + fr) * K + seg * 8;
    const __nv_bfloat16* b_l = Bl + (size_t)(n0 + fr) * K + seg * 8;

    float acc[2][8][4];
#pragma unroll
    for (int i = 0; i < 2; i++)
#pragma unroll
        for (int j = 0; j < 8; j++)
#pragma unroll
            for (int v = 0; v < 4; v++) acc[i][j][v] = 0.0f;

    const uint32_t a_lane_row = (uint32_t)(warp_m * 32 + (lid & 15));
    const uint32_t a_lane_kb = (uint32_t)((lid >> 4) * 16);
    const uint32_t b_lane_row = (uint32_t)(warp_n * 64 + (lid & 7) + ((lid >> 4) & 1) * 8);
    const uint32_t b_lane_kb = (uint32_t)(((lid >> 3) & 1) * 16);

    const uint32_t doff = (uint32_t)(fr * GSTRIDE + seg * 16);

    auto fill = [&](int s, int kc) {
        const uint32_t base = sb + s * STAGE_BYTES;
        const size_t ko = (size_t)kc * 32;
        CP16(base + STG_A_HI + doff, a_h + ko);
        CP16(base + STG_A_HI + doff + 64 * GSTRIDE, a_h + ko + (size_t)64 * K);
        CP16(base + STG_A_LO + doff, a_l + ko);
        CP16(base + STG_A_LO + doff + 64 * GSTRIDE, a_l + ko + (size_t)64 * K);
        CP16(base + STG_B_HI + doff, b_h + ko);
        CP16(base + STG_B_HI + doff + 64 * GSTRIDE, b_h + ko + (size_t)64 * K);
        CP16(base + STG_B_LO + doff, b_l + ko);
        CP16(base + STG_B_LO + doff + 64 * GSTRIDE, b_l + ko + (size_t)64 * K);
    };

    auto do_mma = [&](int s) {
        const uint32_t base = sb + s * STAGE_BYTES;
#pragma unroll
        for (int ks = 0; ks < 2; ks++) {
            uint32_t ah[2][4], al[2][4];
#pragma unroll
            for (int mt = 0; mt < 2; mt++) {
                uint32_t addr = base + STG_A_HI +
                    (a_lane_row + mt * 16) * GSTRIDE + ks * 32 + a_lane_kb;
                LDMATRIX_X4(ah[mt][0], ah[mt][1], ah[mt][2], ah[mt][3], addr);
                LDMATRIX_X4(al[mt][0], al[mt][1], al[mt][2], al[mt][3],
                            addr + (STG_A_LO - STG_A_HI));
            }
#pragma unroll
            for (int pb = 0; pb < 4; pb++) {
                uint32_t bh0[2], bh1[2], bl0[2], bl1[2];
                uint32_t addr = base + STG_B_HI +
                    (b_lane_row + pb * 16) * GSTRIDE + ks * 32 + b_lane_kb;
                LDMATRIX_X4(bh0[0], bh0[1], bh1[0], bh1[1], addr);
                LDMATRIX_X4(bl0[0], bl0[1], bl1[0], bl1[1],
                            addr + (STG_B_LO - STG_B_HI));
#pragma unroll
                for (int mt = 0; mt < 2; mt++) {
                    MMA_BF16(acc[mt][2 * pb], ah[mt], bh0);
                    MMA_BF16(acc[mt][2 * pb], ah[mt], bl0);
                    MMA_BF16(acc[mt][2 * pb], al[mt], bh0);
                    MMA_BF16(acc[mt][2 * pb + 1], ah[mt], bh1);
                    MMA_BF16(acc[mt][2 * pb + 1], ah[mt], bl1);
                    MMA_BF16(acc[mt][2 * pb + 1], al[mt], bh1);
                }
            }
        }
    };

    const int nchunks = K >> 5;
    fill(0, 0);
    CP_COMMIT();

    for (int kc = 0; kc < nchunks; kc++) {
        CP_WAIT0();
        __syncthreads();
        if (kc + 1 < nchunks) {
            fill((kc + 1) & 1, kc + 1);
            CP_COMMIT();
        }
        do_mma(kc & 1);
        __syncthreads();
    }

#pragma unroll
    for (int mt = 0; mt < 2; mt++) {
        int r0 = m0 + warp_m * 32 + mt * 16 + (lid >> 2);
#pragma unroll
        for (int nt = 0; nt < 8; nt++) {
            int col = n0 + warp_n * 64 + nt * 8 + (lid & 3) * 2;
            float2 bv = *(const float2*)(bias + col);
            float c0x = acc[mt][nt][0] + bv.x, c0y = acc[mt][nt][1] + bv.y;
            float c1x = acc[mt][nt][2] + bv.x, c1y = acc[mt][nt][3] + bv.y;
            if (Ch) {
                uint32_t h0, l0, h1, l1;
                split_pack(c0x, c0y, h0, l0);
                split_pack(c1x, c1y, h1, l1);
                *(uint32_t*)(Ch + (size_t)r0 * N + col) = h0;
                *(uint32_t*)(Cl + (size_t)r0 * N + col) = l0;
                *(uint32_t*)(Ch + (size_t)(r0 + 8) * N + col) = h1;
                *(uint32_t*)(Cl + (size_t)(r0 + 8) * N + col) = l1;
            } else {
                *(float2*)(C + (size_t)r0 * N + col) = make_float2(c0x, c0y);
                *(float2*)(C + (size_t)(r0 + 8) * N + col) = make_float2(c1x, c1y);
            }
        }
    }
}

// ---------------------------------------------------------------------------
// Tensor-core flash attention (bf16-split, causal), 128 q-rows per CTA.
// 8 warps x 16 q-rows. K-tiles of 64, cp.async double buffered.
// ---------------------------------------------------------------------------
#define FSTR 144                       // 128B data + 16B pad per row
#define F_QH 0                         // 128 x FSTR
#define F_QL 18432
#define F_STAGE0 36864
#define F_STAGE_BYTES 36864            // KH, KL, VH, VL (64 x FSTR each)
#define F_KH 0
#define F_KL 9216
#define F_VH 18432
#define F_VL 27648
#define FLASH_SMEM (F_STAGE0 + 2 * F_STAGE_BYTES)   // 110592

__global__ void __launch_bounds__(256, 2)
flash_attn_tc_kernel(const __nv_bfloat16* __restrict__ qkvh,
                     const __nv_bfloat16* __restrict__ qkvl,
                     __nv_bfloat16* __restrict__ aoh,
                     __nv_bfloat16* __restrict__ aol) {
    extern __shared__ __align__(16) unsigned char smem[];
    const uint32_t sb = smem_u32(smem);

    const int qt = (int)(gridDim.x - 1 - blockIdx.x);   // heavy tiles first
    const int h  = blockIdx.y;
    const int b  = blockIdx.z;
    const int tid = threadIdx.x;
    const int w = tid >> 5;
    const int l = tid & 31;
    const int g = l >> 2;
    const int t = l & 3;
    const int w16 = w * 16;

    const int q0 = qt * 128;
    const size_t rb = (size_t)b * SS;

    // Q fill: 256 threads cover 128 rows x 2 half-rows (64B each)
    const int fq_r = tid >> 1;
    const int fq_s = tid & 1;
    {
        const __nv_bfloat16* qh_src =
            qkvh + (rb + q0 + fq_r) * (size_t)QKV_N + h * HD + fq_s * 32;
        const __nv_bfloat16* ql_src =
            qkvl + (rb + q0 + fq_r) * (size_t)QKV_N + h * HD + fq_s * 32;
        uint32_t dq = sb + F_QH + fq_r * FSTR + fq_s * 64;
#pragma unroll
        for (int j = 0; j < 4; j++) {
            CP16(dq + j * 16, qh_src + j * 8);
            CP16(dq + (F_QL - F_QH) + j * 16, ql_src + j * 8);
        }
    }

    // KV fill: 256 threads cover 64 rows x 4 quarter-rows (32B each)
    const int fk_r = tid >> 2;
    const int fk_s = tid & 3;
    auto fillKV = [&](int s, int kt) {
        const uint32_t base = sb + F_STAGE0 + s * F_STAGE_BYTES;
        const size_t row = rb + (size_t)kt * 64 + fk_r;
        const __nv_bfloat16* kh = qkvh + row * QKV_N + DD + h * HD + fk_s * 16;
        const __nv_bfloat16* kl = qkvl + row * QKV_N + DD + h * HD + fk_s * 16;
        const __nv_bfloat16* vh = qkvh + row * QKV_N + 2 * DD + h * HD + fk_s * 16;
        const __nv_bfloat16* vl = qkvl + row * QKV_N + 2 * DD + h * HD + fk_s * 16;
        const uint32_t d = fk_r * FSTR + fk_s * 32;
        CP16(base + F_KH + d, kh);
        CP16(base + F_KH + d + 16, kh + 8);
        CP16(base + F_KL + d, kl);
        CP16(base + F_KL + d + 16, kl + 8);
        CP16(base + F_VH + d, vh);
        CP16(base + F_VH + d + 16, vh + 8);
        CP16(base + F_VL + d, vl);
        CP16(base + F_VL + d + 16, vl + 8);
    };

    fillKV(0, 0);
    CP_COMMIT();

    float o[8][4];
#pragma unroll
    for (int j = 0; j < 8; j++)
#pragma unroll
        for (int v = 0; v < 4; v++) o[j][v] = 0.0f;
    float m0 = -INFINITY, m1 = -INFINITY, l0 = 0.0f, l1 = 0.0f;

    const uint32_t a_row = (uint32_t)(w16 + (l & 15));
    const uint32_t a_kb = (uint32_t)((l >> 4) * 16);
    const uint32_t b_row = (uint32_t)((l & 7) + ((l >> 4) & 1) * 8);
    const uint32_t b_kb = (uint32_t)(((l >> 3) & 1) * 16);
    const uint32_t v_row = (uint32_t)(l & 15);
    const uint32_t v_cb = (uint32_t)((l >> 4) * 16);

    const float sc = 0.125f;
    const int ktmax = 2 * qt + 1;

    for (int kt = 0; kt <= ktmax; kt++) {
        __syncthreads();
        if (kt < ktmax) {
            fillKV((kt + 1) & 1, kt + 1);
            CP_COMMIT();
            CP_WAIT1();
        } else {
            CP_WAIT0();
        }
        __syncthreads();

        const uint32_t stg = sb + F_STAGE0 + (kt & 1) * F_STAGE_BYTES;

        // ---- S = Q K^T (split, 3 terms) ----
        float s_[8][4];
#pragma unroll
        for (int j = 0; j < 8; j++)
#pragma unroll
            for (int v = 0; v < 4; v++) s_[j][v] = 0.0f;

#pragma unroll
        for (int ks = 0; ks < 4; ks++) {
            uint32_t qh[4], ql[4];
            uint32_t qaddr = sb + F_QH + a_row * FSTR + ks * 32 + a_kb;
            LDMATRIX_X4(qh[0], qh[1], qh[2], qh[3], qaddr);
            LDMATRIX_X4(ql[0], ql[1], ql[2], ql[3], qaddr + (F_QL - F_QH));
#pragma unroll
            for (int pb = 0; pb < 4; pb++) {
                uint32_t kh0[2], kh1[2], kl0[2], kl1[2];
                uint32_t kaddr = stg + F_KH + (b_row + pb * 16) * FSTR + ks * 32 + b_kb;
                LDMATRIX_X4(kh0[0], kh0[1], kh1[0], kh1[1], kaddr);
                LDMATRIX_X4(kl0[0], kl0[1], kl1[0], kl1[1], kaddr + (F_KL - F_KH));
                MMA_BF16(s_[2 * pb], qh, kh0);
                MMA_BF16(s_[2 * pb], qh, kl0);
                MMA_BF16(s_[2 * pb], ql, kh0);
                MMA_BF16(s_[2 * pb + 1], qh, kh1);
                MMA_BF16(s_[2 * pb + 1], qh, kl1);
                MMA_BF16(s_[2 * pb + 1], ql, kh1);
            }
        }

        // ---- scale + causal mask (global indices) ----
#pragma unroll
        for (int j = 0; j < 8; j++)
#pragma unroll
            for (int v = 0; v < 4; v++) s_[j][v] *= sc;

        const int k0g = kt * 64;
        if (k0g + 63 > q0 + w16) {
            const int lr0 = q0 + w16 + g, lr1 = lr0 + 8;
#pragma unroll
            for (int j = 0; j < 8; j++) {
                int lc = k0g + 8 * j + 2 * t;
                if (lc > lr0) s_[j][0] = -INFINITY;
                if (lc + 1 > lr0) s_[j][1] = -INFINITY;
                if (lc > lr1) s_[j][2] = -INFINITY;
                if (lc + 1 > lr1) s_[j][3] = -INFINITY;
            }
        }

        // ---- online softmax ----
        float tm0 = -INFINITY, tm1 = -INFINITY;
#pragma unroll
        for (int j = 0; j < 8; j++) {
            tm0 = fmaxf(tm0, fmaxf(s_[j][0], s_[j][1]));
            tm1 = fmaxf(tm1, fmaxf(s_[j][2], s_[j][3]));
        }
        tm0 = fmaxf(tm0, __shfl_xor_sync(0xffffffffu, tm0, 1));
        tm0 = fmaxf(tm0, __shfl_xor_sync(0xffffffffu, tm0, 2));
        tm1 = fmaxf(tm1, __shfl_xor_sync(0xffffffffu, tm1, 1));
        tm1 = fmaxf(tm1, __shfl_xor_sync(0xffffffffu, tm1, 2));

        float mn0 = fmaxf(m0, tm0), mn1 = fmaxf(m1, tm1);
        float alpha0 = __expf(m0 - mn0), alpha1 = __expf(m1 - mn1);
        float rs0 = 0.0f, rs1 = 0.0f;
#pragma unroll
        for (int j = 0; j < 8; j++) {
            s_[j][0] = __expf(s_[j][0] - mn0);
            s_[j][1] = __expf(s_[j][1] - mn0);
            s_[j][2] = __expf(s_[j][2] - mn1);
            s_[j][3] = __expf(s_[j][3] - mn1);
            rs0 += s_[j][0] + s_[j][1];
            rs1 += s_[j][2] + s_[j][3];
        }
        rs0 += __shfl_xor_sync(0xffffffffu, rs0, 1);
        rs0 += __shfl_xor_sync(0xffffffffu, rs0, 2);
        rs1 += __shfl_xor_sync(0xffffffffu, rs1, 1);
        rs1 += __shfl_xor_sync(0xffffffffu, rs1, 2);
        l0 = l0 * alpha0 + rs0;
        l1 = l1 * alpha1 + rs1;
        m0 = mn0;
        m1 = mn1;
#pragma unroll
        for (int j = 0; j < 8; j++) {
            o[j][0] *= alpha0;
            o[j][1] *= alpha0;
            o[j][2] *= alpha1;
            o[j][3] *= alpha1;
        }

        // ---- O += P V (split P in-register, V via ldmatrix.trans) ----
#pragma unroll
        for (int s = 0; s < 4; s++) {
            uint32_t ph[4], pl[4];
            split_pack(s_[2 * s][0], s_[2 * s][1], ph[0], pl[0]);
            split_pack(s_[2 * s][2], s_[2 * s][3], ph[1], pl[1]);
            split_pack(s_[2 * s + 1][0], s_[2 * s + 1][1], ph[2], pl[2]);
            split_pack(s_[2 * s + 1][2], s_[2 * s + 1][3], ph[3], pl[3]);
#pragma unroll
            for (int jp = 0; jp < 4; jp++) {
                uint32_t vh[4], vl[4];
                uint32_t vaddr = stg + F_VH + (16 * s + v_row) * FSTR + jp * 32 + v_cb;
                LDMATRIX_X4_T(vh[0], vh[1], vh[2], vh[3], vaddr);
                LDMATRIX_X4_T(vl[0], vl[1], vl[2], vl[3], vaddr + (F_VL - F_VH));
                uint32_t bh0[2] = {vh[0], vh[1]}, bh1[2] = {vh[2], vh[3]};
                uint32_t bl0[2] = {vl[0], vl[1]}, bl1[2] = {vl[2], vl[3]};
                MMA_BF16(o[2 * jp], ph, bh0);
                MMA_BF16(o[2 * jp], ph, bl0);
                MMA_BF16(o[2 * jp], pl, bh0);
                MMA_BF16(o[2 * jp + 1], ph, bh1);
                MMA_BF16(o[2 * jp + 1], ph, bl1);
                MMA_BF16(o[2 * jp + 1], pl, bh1);
            }
        }
    }

    // ---- epilogue ----
    const float inv0 = 1.0f / l0, inv1 = 1.0f / l1;
    const size_t r0 = rb + q0 + w16 + g;
    const size_t r1 = r0 + 8;
#pragma unroll
    for (int j = 0; j < 8; j++) {
        int c = h * HD + 8 * j + 2 * t;
        uint32_t h0, lo0, h1, lo1;
        split_pack(o[j][0] * inv0, o[j][1] * inv0, h0, lo0);
        split_pack(o[j][2] * inv1, o[j][3] * inv1, h1, lo1);
        *(uint32_t*)(aoh + r0 * DD + c) = h0;
        *(uint32_t*)(aol + r0 * DD + c) = lo0;
        *(uint32_t*)(aoh + r1 * DD + c) = h1;
        *(uint32_t*)(aol + r1 * DD + c) = lo1;
    }
}

// ---------------------------------------------------------------------------
// Launch
// ---------------------------------------------------------------------------
extern "C" void kernel_launch(void* const* d_in, const int* in_sizes, int n_in,
                              void* d_out, int out_size) {
    const float* x      = (const float*)d_in[0];
    const float* W_attn = (const float*)d_in[1];
    const float* b_attn = (const float*)d_in[2];
    const float* W_proj = (const float*)d_in[3];
    const float* b_proj = (const float*)d_in[4];
    float* out = (float*)d_out;

    __nv_bfloat16 *qkvh, *qkvl, *xh, *xl, *aoh, *aol, *wah, *wal, *wph, *wpl;
    cudaGetSymbolAddress((void**)&qkvh, g_qkvh);
    cudaGetSymbolAddress((void**)&qkvl, g_qkvl);
    cudaGetSymbolAddress((void**)&xh, g_xh);
    cudaGetSymbolAddress((void**)&xl, g_xl);
    cudaGetSymbolAddress((void**)&aoh, g_aoh);
    cudaGetSymbolAddress((void**)&aol, g_aol);
    cudaGetSymbolAddress((void**)&wah, g_wah);
    cudaGetSymbolAddress((void**)&wal, g_wal);
    cudaGetSymbolAddress((void**)&wph, g_wph);
    cudaGetSymbolAddress((void**)&wpl, g_wpl);

    cudaFuncSetAttribute(gemm_bf16_kernel,
                         cudaFuncAttributeMaxDynamicSharedMemorySize, GEMM_SMEM);
    cudaFuncSetAttribute(flash_attn_tc_kernel,
                         cudaFuncAttributeMaxDynamicSharedMemorySize, FLASH_SMEM);

    // 0) Pre-split inputs
    split_kernel<<<(ROWS * DD / 4) / 256, 256>>>((const float4*)x, (uint2*)xh, (uint2*)xl,
                                                 ROWS * DD / 4);
    split_wT_kernel<<<dim3(QKV_N / 32, DD / 32), dim3(32, 8)>>>(W_attn, wah, wal, DD, QKV_N);
    split_wT_kernel<<<dim3(DD / 32, DD / 32), dim3(32, 8)>>>(W_proj, wph, wpl, DD, DD);

    // 1) QKV projection -> split bf16 output
    {
        dim3 grid(QKV_N / 128, ROWS / 128);
        gemm_bf16_kernel<<<grid, 256, GEMM_SMEM>>>(xh, xl, wah, wal, b_attn,
                                                   nullptr, qkvh, qkvl, QKV_N, DD);
    }
    // 2) Tensor-core flash attention (128-row q tiles)
    {
        dim3 grid(SS / 128, HH, BB);
        flash_attn_tc_kernel<<<grid, 256, FLASH_SMEM>>>(qkvh, qkvl, aoh, aol);
    }
    // 3) Output projection -> fp32 out
    {
        dim3 grid(DD / 128, ROWS / 128);
        gemm_bf16_kernel<<<grid, 256, GEMM_SMEM>>>(aoh, aol, wph, wpl, b_proj,
                                                   out, nullptr, nullptr, DD, DD);
    }
}